// round 4
// baseline (speedup 1.0000x reference)
#include <cuda_runtime.h>

typedef unsigned long long ull;

// packed fp32x2 FMA: d = a*b + d (PTX-only pattern; 2 MACs per lane-slot)
#define FMA2(d, a, b) asm("fma.rn.f32x2 %0, %1, %2, %0;" : "+l"(d) : "l"(a), "l"(b))

// scratch: y[b][s*64+c][h][w] = Blur_s(x[b][c])   (8*192*256*256 f32 = 384 MB)
__device__ float g_v[100663296];
// transposed fusion weights: g_wt[k*64 + o] = wf[o*192 + k], k = s*64+c
__device__ float g_wt[12288];

__device__ __forceinline__ ull bcast2(float v) {
  union { float2 f; ull u; } c;
  c.f.x = v; c.f.y = v;
  return c.u;
}

// ---------------------------------------------------------------------------
// Kernel 0: one-time weight transpose
// ---------------------------------------------------------------------------
__global__ void wt_kernel(const float* __restrict__ wf) {
  int i = blockIdx.x * 256 + threadIdx.x;   // i = o*192 + j
  if (i < 12288) {
    int o = i / 192, j = i - o * 192;
    g_wt[j * 64 + o] = wf[i];
  }
}

// ---------------------------------------------------------------------------
// Kernel 1: separable 3-scale blur. One (b,c) plane, 64x64 output tile.
// x tile (+halo 6) loaded ONCE, shared by all three scales. Horizontal pass
// shares the 13-tap read across scales; vertical pass register-slides.
// ---------------------------------------------------------------------------
__global__ __launch_bounds__(256) void blur_kernel(const float* __restrict__ x) {
  extern __shared__ float sm[];
  float* sv = sm;               // [76][77] raw x tile (+halo), padded stride
  float* hb = sm + 76 * 77;     // [3][76][64] after horizontal pass

  const int t = threadIdx.x;
  const int pl = blockIdx.z;    // b*64 + c
  const int b = pl >> 6, c = pl & 63;
  const int h0 = blockIdx.y << 6, w0 = blockIdx.x << 6;
  const float* xp = x + (size_t)pl * 65536;

  for (int i = t; i < 5776; i += 256) {
    const int r = i / 76, cc = i - r * 76;
    const int hh = h0 - 6 + r, ww = w0 - 6 + cc;
    float v = 0.f;
    if ((unsigned)hh < 256u && (unsigned)ww < 256u) v = xp[hh * 256 + ww];
    sv[r * 77 + cc] = v;
  }
  __syncthreads();

  for (int i = t; i < 4864; i += 256) {
    const int r = i >> 6, j = i & 63;
    const float* p = sv + r * 77 + j;
    const float v0 = p[0], v1 = p[1], v2 = p[2], v3 = p[3], v4 = p[4],
                v5 = p[5], v6 = p[6], v7 = p[7], v8 = p[8], v9 = p[9],
                v10 = p[10], v11 = p[11], v12 = p[12];
    hb[(0 * 76 + r) * 64 + j] = 0.78698604f * v6 + 0.10650698f * (v5 + v7);
    hb[(1 * 76 + r) * 64 + j] = 0.39905028f * v6 + 0.24203623f * (v5 + v7)
                              + 0.05400558f * (v4 + v8) + 0.00443305f * (v3 + v9);
    hb[(2 * 76 + r) * 64 + j] = 0.19967563f * v6 + 0.17621312f * (v5 + v7)
                              + 0.12110939f * (v4 + v8) + 0.06482519f * (v3 + v9)
                              + 0.02702316f * (v2 + v10) + 0.00877314f * (v1 + v11)
                              + 0.00221820f * (v0 + v12);
  }
  __syncthreads();

  const int j = t & 63, rg = t >> 6;
  const int base = rg << 4;                 // 16 output rows per thread
  const size_t prow = (size_t)(h0 + base) * 256 + w0 + j;
  float* y0 = g_v + (size_t)(b * 192 + c) * 65536 + prow;
  float* y1 = g_v + (size_t)(b * 192 + 64 + c) * 65536 + prow;
  float* y2 = g_v + (size_t)(b * 192 + 128 + c) * 65536 + prow;

  float a2[13], a1[7], a0[3];
  #pragma unroll
  for (int d = 0; d < 12; d++) a2[d] = hb[(2 * 76 + base + d) * 64 + j];
  #pragma unroll
  for (int d = 0; d < 6; d++) a1[d] = hb[(1 * 76 + base + 3 + d) * 64 + j];
  a0[0] = hb[(0 * 76 + base + 5) * 64 + j];
  a0[1] = hb[(0 * 76 + base + 6) * 64 + j];

  #pragma unroll
  for (int i2 = 0; i2 < 16; i2++) {
    a2[12] = hb[(2 * 76 + base + i2 + 12) * 64 + j];
    a1[6]  = hb[(1 * 76 + base + i2 + 9) * 64 + j];
    a0[2]  = hb[(0 * 76 + base + i2 + 7) * 64 + j];
    y0[i2 * 256] = 0.78698604f * a0[1] + 0.10650698f * (a0[0] + a0[2]);
    y1[i2 * 256] = 0.39905028f * a1[3] + 0.24203623f * (a1[2] + a1[4])
                 + 0.05400558f * (a1[1] + a1[5]) + 0.00443305f * (a1[0] + a1[6]);
    y2[i2 * 256] = 0.19967563f * a2[6] + 0.17621312f * (a2[5] + a2[7])
                 + 0.12110939f * (a2[4] + a2[8]) + 0.06482519f * (a2[3] + a2[9])
                 + 0.02702316f * (a2[2] + a2[10]) + 0.00877314f * (a2[1] + a2[11])
                 + 0.00221820f * (a2[0] + a2[12]);
    #pragma unroll
    for (int d = 0; d < 12; d++) a2[d] = a2[d + 1];
    #pragma unroll
    for (int d = 0; d < 6; d++) a1[d] = a1[d + 1];
    a0[0] = a0[1]; a0[1] = a0[2];
  }
}

// ---------------------------------------------------------------------------
// Kernel 2: fused 1x1 conv (M=64, K=192) + bias + residual.
// Warp tile: 64 m x 16 px. Lane owns m={2*lane, 2*lane+1}; pixels are uniform
// across the warp, so B comes as broadcast LDG.128 from the y-plane — the
// float4 IS two f32x2 operands (zero pack instrs). A is one LDS.64 + 2 packs
// per k. Depth-2 LDG prefetch hides DRAM/L2 latency. Only W lives in smem.
// ---------------------------------------------------------------------------
__global__ __launch_bounds__(256, 2) void fuse_kernel(
    const float* __restrict__ x, const float* __restrict__ fb,
    float* __restrict__ out) {
  __shared__ float sW[12288];   // [192][64]: sW[k*64 + m]  (48 KB)

  const int t = threadIdx.x;
  const int lane = t & 31, w = t >> 5;
  const int b = blockIdx.x >> 9;
  const int px0 = ((blockIdx.x & 511) << 7) + (w << 4);   // 16 px per warp

  // stage weights (coalesced, conflict-free)
  {
    const float4* wsrc = (const float4*)g_wt;
    float4* wdst = (float4*)sW;
    #pragma unroll
    for (int i = 0; i < 12; i++) wdst[t + i * 256] = wsrc[t + i * 256];
  }
  __syncthreads();

  const float* yb = g_v + (size_t)b * 192 * 65536 + px0;  // + k*65536

  // prefetch buffers: k and k+1 (4x float4 = 16 px each)
  float4 buf[2][4];
  #pragma unroll
  for (int q = 0; q < 4; q++) buf[0][q] = __ldg((const float4*)(yb) + q);
  #pragma unroll
  for (int q = 0; q < 4; q++) buf[1][q] = __ldg((const float4*)(yb + 65536) + q);

  ull accL[8], accH[8];
  #pragma unroll
  for (int i = 0; i < 8; i++) { accL[i] = 0ULL; accH[i] = 0ULL; }

  const float* wp = sW + 2 * lane;

  #pragma unroll 2
  for (int k = 0; k < 192; k++) {
    const float2 wv = *(const float2*)(wp + k * 64);
    const ull aL = bcast2(wv.x), aH = bcast2(wv.y);
    const int sel = k & 1;
    ull bv[8];
    #pragma unroll
    for (int q = 0; q < 4; q++) {
      union { float4 f; ull u[2]; } cv;
      cv.f = buf[sel][q];
      bv[2 * q] = cv.u[0]; bv[2 * q + 1] = cv.u[1];
    }
    // prefetch k+2 into the slot just consumed (clamped to stay in-plane)
    const int kn = (k + 2 < 192) ? (k + 2) : 191;
    const float4* src = (const float4*)(yb + (size_t)kn * 65536);
    #pragma unroll
    for (int q = 0; q < 4; q++) buf[sel][q] = __ldg(src + q);

    #pragma unroll
    for (int p = 0; p < 8; p++) {
      FMA2(accL[p], aL, bv[p]);
      FMA2(accH[p], aH, bv[p]);
    }
  }

  // epilogue: out = x + bias + acc, rows m=2*lane and 2*lane+1, 16 px each
  const int m = lane << 1;
  const float bL = __ldg(fb + m), bH = __ldg(fb + m + 1);
  const float* xr = x + ((size_t)(b << 6) + m) * 65536 + px0;
  float* orr = out + ((size_t)(b << 6) + m) * 65536 + px0;
  #pragma unroll
  for (int q = 0; q < 4; q++) {
    union { ull u; float2 f; } c0, c1;
    c0.u = accL[2 * q]; c1.u = accL[2 * q + 1];
    const float4 xv = *(const float4*)(xr + 4 * q);
    *(float4*)(orr + 4 * q) = make_float4(xv.x + bL + c0.f.x, xv.y + bL + c0.f.y,
                                          xv.z + bL + c1.f.x, xv.w + bL + c1.f.y);
  }
  const float* xr2 = xr + 65536;
  float* or2 = orr + 65536;
  #pragma unroll
  for (int q = 0; q < 4; q++) {
    union { ull u; float2 f; } c0, c1;
    c0.u = accH[2 * q]; c1.u = accH[2 * q + 1];
    const float4 xv = *(const float4*)(xr2 + 4 * q);
    *(float4*)(or2 + 4 * q) = make_float4(xv.x + bH + c0.f.x, xv.y + bH + c0.f.y,
                                          xv.z + bH + c1.f.x, xv.w + bH + c1.f.y);
  }
}

// ---------------------------------------------------------------------------
extern "C" void kernel_launch(void* const* d_in, const int* in_sizes, int n_in,
                              void* d_out, int out_size) {
  const float* x  = (const float*)d_in[0];   // [8,64,256,256] f32
  const float* wf = (const float*)d_in[1];   // [64,192] f32
  const float* fb = (const float*)d_in[2];   // [64] f32
  float* out = (float*)d_out;                // [8,64,256,256] f32

  wt_kernel<<<48, 256>>>(wf);

  cudaFuncSetAttribute(blur_kernel,
                       cudaFuncAttributeMaxDynamicSharedMemorySize, 81776);
  blur_kernel<<<dim3(4, 4, 512), 256, 81776>>>(x);

  fuse_kernel<<<4096, 256>>>(x, fb, out);
}

// round 7
// speedup vs baseline: 2.0526x; 2.0526x over previous
#include <cuda_runtime.h>

typedef unsigned long long ull;

// packed fp32x2 FMA: d = a*b + d (PTX-only pattern; 2 MACs per lane-slot)
#define FMA2(d, a, b) asm("fma.rn.f32x2 %0, %1, %2, %0;" : "+l"(d) : "l"(a), "l"(b))

// scratch: y[b][s*64+c][h][w] = Blur_s(x[b][c])   (8*192*256*256 f32 = 384 MB)
__device__ float g_v[100663296];
// transposed fusion weights: g_wt[k*64 + o] = wf[o*192 + k], k = s*64+c
__device__ float g_wt[12288];

__device__ __forceinline__ ull bcast2(float v) {
  union { float2 f; ull u; } c;
  c.f.x = v; c.f.y = v;
  return c.u;
}

// ---------------------------------------------------------------------------
// Kernel 0: one-time weight transpose
// ---------------------------------------------------------------------------
__global__ void wt_kernel(const float* __restrict__ wf) {
  int i = blockIdx.x * 256 + threadIdx.x;   // i = o*192 + j
  if (i < 12288) {
    int o = i / 192, j = i - o * 192;
    g_wt[j * 64 + o] = wf[i];
  }
}

// ---------------------------------------------------------------------------
// Kernel 1: separable 3-scale blur (unchanged from R3 — proven).
// One (b,c) plane, 64x64 output tile; x tile (+halo 6) loaded once, shared by
// all three scales; vertical pass register-slides.
// ---------------------------------------------------------------------------
__global__ __launch_bounds__(256) void blur_kernel(const float* __restrict__ x) {
  extern __shared__ float sm[];
  float* sv = sm;               // [76][77] raw x tile (+halo), padded stride
  float* hb = sm + 76 * 77;     // [3][76][64] after horizontal pass

  const int t = threadIdx.x;
  const int pl = blockIdx.z;    // b*64 + c
  const int b = pl >> 6, c = pl & 63;
  const int h0 = blockIdx.y << 6, w0 = blockIdx.x << 6;
  const float* xp = x + (size_t)pl * 65536;

  for (int i = t; i < 5776; i += 256) {
    const int r = i / 76, cc = i - r * 76;
    const int hh = h0 - 6 + r, ww = w0 - 6 + cc;
    float v = 0.f;
    if ((unsigned)hh < 256u && (unsigned)ww < 256u) v = xp[hh * 256 + ww];
    sv[r * 77 + cc] = v;
  }
  __syncthreads();

  for (int i = t; i < 4864; i += 256) {
    const int r = i >> 6, j = i & 63;
    const float* p = sv + r * 77 + j;
    const float v0 = p[0], v1 = p[1], v2 = p[2], v3 = p[3], v4 = p[4],
                v5 = p[5], v6 = p[6], v7 = p[7], v8 = p[8], v9 = p[9],
                v10 = p[10], v11 = p[11], v12 = p[12];
    hb[(0 * 76 + r) * 64 + j] = 0.78698604f * v6 + 0.10650698f * (v5 + v7);
    hb[(1 * 76 + r) * 64 + j] = 0.39905028f * v6 + 0.24203623f * (v5 + v7)
                              + 0.05400558f * (v4 + v8) + 0.00443305f * (v3 + v9);
    hb[(2 * 76 + r) * 64 + j] = 0.19967563f * v6 + 0.17621312f * (v5 + v7)
                              + 0.12110939f * (v4 + v8) + 0.06482519f * (v3 + v9)
                              + 0.02702316f * (v2 + v10) + 0.00877314f * (v1 + v11)
                              + 0.00221820f * (v0 + v12);
  }
  __syncthreads();

  const int j = t & 63, rg = t >> 6;
  const int base = rg << 4;                 // 16 output rows per thread
  const size_t prow = (size_t)(h0 + base) * 256 + w0 + j;
  float* y0 = g_v + (size_t)(b * 192 + c) * 65536 + prow;
  float* y1 = g_v + (size_t)(b * 192 + 64 + c) * 65536 + prow;
  float* y2 = g_v + (size_t)(b * 192 + 128 + c) * 65536 + prow;

  float a2[13], a1[7], a0[3];
  #pragma unroll
  for (int d = 0; d < 12; d++) a2[d] = hb[(2 * 76 + base + d) * 64 + j];
  #pragma unroll
  for (int d = 0; d < 6; d++) a1[d] = hb[(1 * 76 + base + 3 + d) * 64 + j];
  a0[0] = hb[(0 * 76 + base + 5) * 64 + j];
  a0[1] = hb[(0 * 76 + base + 6) * 64 + j];

  #pragma unroll
  for (int i2 = 0; i2 < 16; i2++) {
    a2[12] = hb[(2 * 76 + base + i2 + 12) * 64 + j];
    a1[6]  = hb[(1 * 76 + base + i2 + 9) * 64 + j];
    a0[2]  = hb[(0 * 76 + base + i2 + 7) * 64 + j];
    y0[i2 * 256] = 0.78698604f * a0[1] + 0.10650698f * (a0[0] + a0[2]);
    y1[i2 * 256] = 0.39905028f * a1[3] + 0.24203623f * (a1[2] + a1[4])
                 + 0.05400558f * (a1[1] + a1[5]) + 0.00443305f * (a1[0] + a1[6]);
    y2[i2 * 256] = 0.19967563f * a2[6] + 0.17621312f * (a2[5] + a2[7])
                 + 0.12110939f * (a2[4] + a2[8]) + 0.06482519f * (a2[3] + a2[9])
                 + 0.02702316f * (a2[2] + a2[10]) + 0.00877314f * (a2[1] + a2[11])
                 + 0.00221820f * (a2[0] + a2[12]);
    #pragma unroll
    for (int d = 0; d < 12; d++) a2[d] = a2[d + 1];
    #pragma unroll
    for (int d = 0; d < 6; d++) a1[d] = a1[d + 1];
    a0[0] = a0[1]; a0[1] = a0[2];
  }
}

// ---------------------------------------------------------------------------
// Kernel 2: fused 1x1 conv (M=64, K=192) + bias + residual.
// Block: 64 m x 128 px, 256 threads, 2 CTA/SM (96 KB smem via k-chunking).
// Lane owns m-pair {2*lane, 2*lane+1} (warp spans all 64 m); warp owns 16 px.
// Per thread-k: A = 1 LDS.64 (lane-strided, 2 wf) + 2 packs;
//               B = 4 broadcast LDS.128 (1 wf each, float4 == two f32x2);
//               16 FMA2.  Per SM: 96 LDS-wf/k < 128 fma-cyc/k -> FMA-bound.
// ---------------------------------------------------------------------------
__global__ __launch_bounds__(256, 2) void fuse_kernel(
    const float* __restrict__ x, const float* __restrict__ fb,
    float* __restrict__ out) {
  extern __shared__ float sm2[];
  float* sW = sm2;              // [192][64]: sW[k*64 + m]     (48 KB)
  float* sY = sm2 + 12288;      // [96][128]: k-chunk of y     (48 KB)

  const int t = threadIdx.x;
  const int lane = t & 31, w = t >> 5;
  const int b = blockIdx.x >> 9;
  const int px0 = (blockIdx.x & 511) << 7;      // 128 px per block

  // stage all weights once (coalesced, conflict-free)
  {
    const float4* wsrc = (const float4*)g_wt;
    float4* wdst = (float4*)sW;
    #pragma unroll
    for (int i = 0; i < 12; i++) wdst[t + i * 256] = wsrc[t + i * 256];
  }

  ull acc[2][8];                // [m-pair half][px-pair]
  #pragma unroll
  for (int r = 0; r < 2; r++)
    #pragma unroll
    for (int p = 0; p < 8; p++) acc[r][p] = 0ULL;

  const float* yb = g_v + (size_t)b * 192 * 65536 + px0;
  const float* wlane = sW + (lane << 1);
  const float* yrow0 = sY + (w << 4);           // this warp's 16-px window

  #pragma unroll
  for (int ch = 0; ch < 2; ch++) {
    // stage y chunk: rows ch*96 .. ch*96+95, 128 px each (32 float4/row)
    __syncthreads();            // protect previous chunk's readers
    {
      const float* src = yb + (size_t)(ch * 96) * 65536;
      #pragma unroll
      for (int i = 0; i < 12; i++) {
        const int idx = t + i * 256;            // 0..3071 float4 slots
        const int kk = idx >> 5, f = idx & 31;
        ((float4*)(sY + kk * 128))[f] =
            *(const float4*)(src + (size_t)kk * 65536 + f * 4);
      }
    }
    __syncthreads();

    const float* wp = wlane + (ch * 96) * 64;
    const float* yp = yrow0;
    #pragma unroll 4
    for (int kk = 0; kk < 96; kk++) {
      const float2 wv = *(const float2*)(wp);   // lane's m-pair weights
      const ull aL = bcast2(wv.x), aH = bcast2(wv.y);
      union { float4 f; ull u[2]; } b0, b1, b2, b3;
      b0.f = ((const float4*)yp)[0];            // warp-uniform 16 px
      b1.f = ((const float4*)yp)[1];
      b2.f = ((const float4*)yp)[2];
      b3.f = ((const float4*)yp)[3];
      FMA2(acc[0][0], aL, b0.u[0]); FMA2(acc[1][0], aH, b0.u[0]);
      FMA2(acc[0][1], aL, b0.u[1]); FMA2(acc[1][1], aH, b0.u[1]);
      FMA2(acc[0][2], aL, b1.u[0]); FMA2(acc[1][2], aH, b1.u[0]);
      FMA2(acc[0][3], aL, b1.u[1]); FMA2(acc[1][3], aH, b1.u[1]);
      FMA2(acc[0][4], aL, b2.u[0]); FMA2(acc[1][4], aH, b2.u[0]);
      FMA2(acc[0][5], aL, b2.u[1]); FMA2(acc[1][5], aH, b2.u[1]);
      FMA2(acc[0][6], aL, b3.u[0]); FMA2(acc[1][6], aH, b3.u[0]);
      FMA2(acc[0][7], aL, b3.u[1]); FMA2(acc[1][7], aH, b3.u[1]);
      wp += 64;
      yp += 128;
    }
  }

  // epilogue: out = x + bias + acc for rows m=2*lane, 2*lane+1; 16 px (warp w)
  const int m = lane << 1;
  const int pxw = px0 + (w << 4);
  const float bL = __ldg(fb + m), bH = __ldg(fb + m + 1);
  const float* xr = x + ((size_t)(b << 6) + m) * 65536 + pxw;
  float* orr = out + ((size_t)(b << 6) + m) * 65536 + pxw;
  #pragma unroll
  for (int q = 0; q < 4; q++) {
    union { ull u; float2 f; } c0, c1;
    c0.u = acc[0][2 * q]; c1.u = acc[0][2 * q + 1];
    const float4 xv = *(const float4*)(xr + 4 * q);
    *(float4*)(orr + 4 * q) = make_float4(xv.x + bL + c0.f.x, xv.y + bL + c0.f.y,
                                          xv.z + bL + c1.f.x, xv.w + bL + c1.f.y);
  }
  const float* xr2 = xr + 65536;
  float* or2 = orr + 65536;
  #pragma unroll
  for (int q = 0; q < 4; q++) {
    union { ull u; float2 f; } c0, c1;
    c0.u = acc[1][2 * q]; c1.u = acc[1][2 * q + 1];
    const float4 xv = *(const float4*)(xr2 + 4 * q);
    *(float4*)(or2 + 4 * q) = make_float4(xv.x + bH + c0.f.x, xv.y + bH + c0.f.y,
                                          xv.z + bH + c1.f.x, xv.w + bH + c1.f.y);
  }
}

// ---------------------------------------------------------------------------
extern "C" void kernel_launch(void* const* d_in, const int* in_sizes, int n_in,
                              void* d_out, int out_size) {
  const float* x  = (const float*)d_in[0];   // [8,64,256,256] f32
  const float* wf = (const float*)d_in[1];   // [64,192] f32
  const float* fb = (const float*)d_in[2];   // [64] f32
  float* out = (float*)d_out;                // [8,64,256,256] f32

  wt_kernel<<<48, 256>>>(wf);

  cudaFuncSetAttribute(blur_kernel,
                       cudaFuncAttributeMaxDynamicSharedMemorySize, 81776);
  blur_kernel<<<dim3(4, 4, 512), 256, 81776>>>(x);

  cudaFuncSetAttribute(fuse_kernel,
                       cudaFuncAttributeMaxDynamicSharedMemorySize, 98304);
  fuse_kernel<<<4096, 256, 98304>>>(x, fb, out);
}

// round 10
// speedup vs baseline: 2.5851x; 1.2594x over previous
#include <cuda_runtime.h>
#include <cstdint>

// scratch: y[b][s*64+c][h][w] = Blur_s(x[b][c])   (8*192*256*256 f32 = 384 MB)
__device__ float g_v[100663296];

// ---------------------------------------------------------------------------
// Kernel 1: separable 3-scale blur (unchanged — proven).
// ---------------------------------------------------------------------------
__global__ __launch_bounds__(256) void blur_kernel(const float* __restrict__ x) {
  extern __shared__ float sm[];
  float* sv = sm;               // [76][77] raw x tile (+halo), padded stride
  float* hb = sm + 76 * 77;     // [3][76][64] after horizontal pass

  const int t = threadIdx.x;
  const int pl = blockIdx.z;    // b*64 + c
  const int b = pl >> 6, c = pl & 63;
  const int h0 = blockIdx.y << 6, w0 = blockIdx.x << 6;
  const float* xp = x + (size_t)pl * 65536;

  for (int i = t; i < 5776; i += 256) {
    const int r = i / 76, cc = i - r * 76;
    const int hh = h0 - 6 + r, ww = w0 - 6 + cc;
    float v = 0.f;
    if ((unsigned)hh < 256u && (unsigned)ww < 256u) v = xp[hh * 256 + ww];
    sv[r * 77 + cc] = v;
  }
  __syncthreads();

  for (int i = t; i < 4864; i += 256) {
    const int r = i >> 6, j = i & 63;
    const float* p = sv + r * 77 + j;
    const float v0 = p[0], v1 = p[1], v2 = p[2], v3 = p[3], v4 = p[4],
                v5 = p[5], v6 = p[6], v7 = p[7], v8 = p[8], v9 = p[9],
                v10 = p[10], v11 = p[11], v12 = p[12];
    hb[(0 * 76 + r) * 64 + j] = 0.78698604f * v6 + 0.10650698f * (v5 + v7);
    hb[(1 * 76 + r) * 64 + j] = 0.39905028f * v6 + 0.24203623f * (v5 + v7)
                              + 0.05400558f * (v4 + v8) + 0.00443305f * (v3 + v9);
    hb[(2 * 76 + r) * 64 + j] = 0.19967563f * v6 + 0.17621312f * (v5 + v7)
                              + 0.12110939f * (v4 + v8) + 0.06482519f * (v3 + v9)
                              + 0.02702316f * (v2 + v10) + 0.00877314f * (v1 + v11)
                              + 0.00221820f * (v0 + v12);
  }
  __syncthreads();

  const int j = t & 63, rg = t >> 6;
  const int base = rg << 4;
  const size_t prow = (size_t)(h0 + base) * 256 + w0 + j;
  float* y0 = g_v + (size_t)(b * 192 + c) * 65536 + prow;
  float* y1 = g_v + (size_t)(b * 192 + 64 + c) * 65536 + prow;
  float* y2 = g_v + (size_t)(b * 192 + 128 + c) * 65536 + prow;

  float a2[13], a1[7], a0[3];
  #pragma unroll
  for (int d = 0; d < 12; d++) a2[d] = hb[(2 * 76 + base + d) * 64 + j];
  #pragma unroll
  for (int d = 0; d < 6; d++) a1[d] = hb[(1 * 76 + base + 3 + d) * 64 + j];
  a0[0] = hb[(0 * 76 + base + 5) * 64 + j];
  a0[1] = hb[(0 * 76 + base + 6) * 64 + j];

  #pragma unroll
  for (int i2 = 0; i2 < 16; i2++) {
    a2[12] = hb[(2 * 76 + base + i2 + 12) * 64 + j];
    a1[6]  = hb[(1 * 76 + base + i2 + 9) * 64 + j];
    a0[2]  = hb[(0 * 76 + base + i2 + 7) * 64 + j];
    y0[i2 * 256] = 0.78698604f * a0[1] + 0.10650698f * (a0[0] + a0[2]);
    y1[i2 * 256] = 0.39905028f * a1[3] + 0.24203623f * (a1[2] + a1[4])
                 + 0.05400558f * (a1[1] + a1[5]) + 0.00443305f * (a1[0] + a1[6]);
    y2[i2 * 256] = 0.19967563f * a2[6] + 0.17621312f * (a2[5] + a2[7])
                 + 0.12110939f * (a2[4] + a2[8]) + 0.06482519f * (a2[3] + a2[9])
                 + 0.02702316f * (a2[2] + a2[10]) + 0.00877314f * (a2[1] + a2[11])
                 + 0.00221820f * (a2[0] + a2[12]);
    #pragma unroll
    for (int d = 0; d < 12; d++) a2[d] = a2[d + 1];
    #pragma unroll
    for (int d = 0; d < 6; d++) a1[d] = a1[d + 1];
    a0[0] = a0[1]; a0[1] = a0[2];
  }
}

// ---------------------------------------------------------------------------
// Kernel 2: fused 1x1 conv via mma.sync tf32 (sm_80-class HMMA, available at
// base sm_103 target) + bias + residual.
// CTA = 128 px x 64 out; warp = m16 (px) x n64 x k192 -> 24 k-steps x 8 n-tiles.
// A staged [px][k] stride 196 (conflict-free a-frag LDS.32, aligned STS.128);
// B staged in fragment order (one LDS.64 per frag). tf32 cvt done at staging.
// ---------------------------------------------------------------------------
#define SA_STR   196
#define SMF_B    100352                   // 128*196*4
#define SMF_FB   149504                   // + 24*8*32*8
#define SMF_TOT  149760

__device__ __forceinline__ uint32_t f2tf32(float f) {
  uint32_t u = __float_as_uint(f);
  asm("cvt.rna.tf32.f32 %0, %1;" : "=r"(u) : "r"(u));
  return u;
}

__global__ __launch_bounds__(256, 1) void fuse_mma_kernel(
    const float* __restrict__ x, const float* __restrict__ wf,
    const float* __restrict__ fb, float* __restrict__ out) {
  extern __shared__ char smc[];
  float* sA = (float*)smc;                 // [128][196] tf32-in-f32 slots
  float2* sB = (float2*)(smc + SMF_B);     // [24][8][32] {b0,b1} fragments
  float* sFB = (float*)(smc + SMF_FB);

  const int t = threadIdx.x;
  const int lane = t & 31, w = t >> 5;
  const int g = lane >> 2, cc = lane & 3;
  const int b = blockIdx.x >> 9;
  const int px0 = (blockIdx.x & 511) << 7;

  if (t < 64) sFB[t] = fb[t];

  // stage B fragments: sB[kk*256 + j*32 + lane] = {W[o][k], W[o][k+4]}, tf32
  #pragma unroll
  for (int i = 0; i < 24; i++) {
    const int idx = i * 256 + t;
    const int kk = idx >> 8, rem = idx & 255;
    const int jj = rem >> 5, ln = rem & 31;
    const int o = (jj << 3) + (ln >> 2), k = (kk << 3) + (ln & 3);
    const uint32_t b0 = f2tf32(wf[o * 192 + k]);
    const uint32_t b1 = f2tf32(wf[o * 192 + k + 4]);
    sB[idx] = make_float2(__uint_as_float(b0), __uint_as_float(b1));
  }

  // stage A: y tile [128 px][192 k], transposed gather of 4 k's per item
  const float* yb = g_v + (size_t)b * 192 * 65536 + px0;
  #pragma unroll
  for (int i = 0; i < 24; i++) {
    const int idx = i * 256 + t;
    const int px = idx & 127, kq = idx >> 7;     // kq in [0,48)
    const float* src = yb + (size_t)(kq << 2) * 65536 + px;
    float4 v;
    v.x = __uint_as_float(f2tf32(src[0]));
    v.y = __uint_as_float(f2tf32(src[65536]));
    v.z = __uint_as_float(f2tf32(src[131072]));
    v.w = __uint_as_float(f2tf32(src[196608]));
    *(float4*)(sA + px * SA_STR + (kq << 2)) = v;   // 784*px+16*kq: 16B-aligned
  }
  __syncthreads();

  const int rowbase = (w << 4) + g;               // warp's first px row
  float acc[8][4];
  #pragma unroll
  for (int j = 0; j < 8; j++)
    #pragma unroll
    for (int q = 0; q < 4; q++) acc[j][q] = 0.f;

  #pragma unroll 4
  for (int kk = 0; kk < 24; kk++) {
    const float* ap = sA + rowbase * SA_STR + (kk << 3) + cc;
    const uint32_t a0 = __float_as_uint(ap[0]);
    const uint32_t a2 = __float_as_uint(ap[4]);
    const uint32_t a1 = __float_as_uint(ap[8 * SA_STR]);
    const uint32_t a3 = __float_as_uint(ap[8 * SA_STR + 4]);
    const float2* bp = sB + (kk << 8) + lane;
    #pragma unroll
    for (int j = 0; j < 8; j++) {
      const float2 bv = bp[j << 5];
      const uint32_t b0 = __float_as_uint(bv.x), b1 = __float_as_uint(bv.y);
      asm volatile(
          "mma.sync.aligned.m16n8k8.row.col.f32.tf32.tf32.f32 "
          "{%0,%1,%2,%3}, {%4,%5,%6,%7}, {%8,%9}, {%0,%1,%2,%3};"
          : "+f"(acc[j][0]), "+f"(acc[j][1]), "+f"(acc[j][2]), "+f"(acc[j][3])
          : "r"(a0), "r"(a1), "r"(a2), "r"(a3), "r"(b0), "r"(b1));
    }
  }

  // epilogue: D[px][o] -> out = x + bias + acc
  // thread holds: rows pxg, pxg+8; cols o0=8j+2c, o1=o0+1
  const int pxg = px0 + rowbase;
  const size_t bb = (size_t)(b << 6) * 65536;
  #pragma unroll
  for (int j = 0; j < 8; j++) {
    const int o0 = (j << 3) + (cc << 1), o1 = o0 + 1;
    const float fb0 = sFB[o0], fb1 = sFB[o1];
    const size_t a0i = bb + (size_t)o0 * 65536 + pxg;
    const size_t a1i = bb + (size_t)o1 * 65536 + pxg;
    out[a0i]     = x[a0i]     + fb0 + acc[j][0];
    out[a1i]     = x[a1i]     + fb1 + acc[j][1];
    out[a0i + 8] = x[a0i + 8] + fb0 + acc[j][2];
    out[a1i + 8] = x[a1i + 8] + fb1 + acc[j][3];
  }
}

// ---------------------------------------------------------------------------
extern "C" void kernel_launch(void* const* d_in, const int* in_sizes, int n_in,
                              void* d_out, int out_size) {
  const float* x  = (const float*)d_in[0];   // [8,64,256,256] f32
  const float* wf = (const float*)d_in[1];   // [64,192] f32
  const float* fb = (const float*)d_in[2];   // [64] f32
  float* out = (float*)d_out;                // [8,64,256,256] f32

  cudaFuncSetAttribute(blur_kernel,
                       cudaFuncAttributeMaxDynamicSharedMemorySize, 81776);
  blur_kernel<<<dim3(4, 4, 512), 256, 81776>>>(x);

  cudaFuncSetAttribute(fuse_mma_kernel,
                       cudaFuncAttributeMaxDynamicSharedMemorySize, SMF_TOT);
  fuse_mma_kernel<<<4096, 256, SMF_TOT>>>(x, wf, fb, out);
}

// round 11
// speedup vs baseline: 3.3641x; 1.3014x over previous
#include <cuda_runtime.h>
#include <cuda_fp16.h>
#include <cstdint>

// scratch: y[b][s*64+c][h][w] = Blur_s(x[b][c])  fp16 (8*192*256*256 = 192 MB)
__device__ __half g_v[100663296];

__device__ __forceinline__ uint32_t smem_u32(const void* p) {
  uint32_t a;
  asm("{ .reg .u64 t; cvta.to.shared.u64 t, %1; cvt.u32.u64 %0, t; }"
      : "=r"(a) : "l"(p));
  return a;
}

// ---------------------------------------------------------------------------
// Kernel 1: separable 3-scale blur (R3-proven structure; fp16 output).
// ---------------------------------------------------------------------------
__global__ __launch_bounds__(256) void blur_kernel(const float* __restrict__ x) {
  extern __shared__ float sm[];
  float* sv = sm;               // [76][77] raw x tile (+halo), padded stride
  float* hb = sm + 76 * 77;     // [3][76][64] after horizontal pass

  const int t = threadIdx.x;
  const int pl = blockIdx.z;    // b*64 + c
  const int b = pl >> 6, c = pl & 63;
  const int h0 = blockIdx.y << 6, w0 = blockIdx.x << 6;
  const float* xp = x + (size_t)pl * 65536;

  for (int i = t; i < 5776; i += 256) {
    const int r = i / 76, cc = i - r * 76;
    const int hh = h0 - 6 + r, ww = w0 - 6 + cc;
    float v = 0.f;
    if ((unsigned)hh < 256u && (unsigned)ww < 256u) v = xp[hh * 256 + ww];
    sv[r * 77 + cc] = v;
  }
  __syncthreads();

  for (int i = t; i < 4864; i += 256) {
    const int r = i >> 6, j = i & 63;
    const float* p = sv + r * 77 + j;
    const float v0 = p[0], v1 = p[1], v2 = p[2], v3 = p[3], v4 = p[4],
                v5 = p[5], v6 = p[6], v7 = p[7], v8 = p[8], v9 = p[9],
                v10 = p[10], v11 = p[11], v12 = p[12];
    hb[(0 * 76 + r) * 64 + j] = 0.78698604f * v6 + 0.10650698f * (v5 + v7);
    hb[(1 * 76 + r) * 64 + j] = 0.39905028f * v6 + 0.24203623f * (v5 + v7)
                              + 0.05400558f * (v4 + v8) + 0.00443305f * (v3 + v9);
    hb[(2 * 76 + r) * 64 + j] = 0.19967563f * v6 + 0.17621312f * (v5 + v7)
                              + 0.12110939f * (v4 + v8) + 0.06482519f * (v3 + v9)
                              + 0.02702316f * (v2 + v10) + 0.00877314f * (v1 + v11)
                              + 0.00221820f * (v0 + v12);
  }
  __syncthreads();

  const int j = t & 63, rg = t >> 6;
  const int base = rg << 4;
  const size_t prow = (size_t)(h0 + base) * 256 + w0 + j;
  __half* y0 = g_v + (size_t)(b * 192 + c) * 65536 + prow;
  __half* y1 = g_v + (size_t)(b * 192 + 64 + c) * 65536 + prow;
  __half* y2 = g_v + (size_t)(b * 192 + 128 + c) * 65536 + prow;

  float a2[13], a1[7], a0[3];
  #pragma unroll
  for (int d = 0; d < 12; d++) a2[d] = hb[(2 * 76 + base + d) * 64 + j];
  #pragma unroll
  for (int d = 0; d < 6; d++) a1[d] = hb[(1 * 76 + base + 3 + d) * 64 + j];
  a0[0] = hb[(0 * 76 + base + 5) * 64 + j];
  a0[1] = hb[(0 * 76 + base + 6) * 64 + j];

  #pragma unroll
  for (int i2 = 0; i2 < 16; i2++) {
    a2[12] = hb[(2 * 76 + base + i2 + 12) * 64 + j];
    a1[6]  = hb[(1 * 76 + base + i2 + 9) * 64 + j];
    a0[2]  = hb[(0 * 76 + base + i2 + 7) * 64 + j];
    y0[i2 * 256] = __float2half_rn(
        0.78698604f * a0[1] + 0.10650698f * (a0[0] + a0[2]));
    y1[i2 * 256] = __float2half_rn(
        0.39905028f * a1[3] + 0.24203623f * (a1[2] + a1[4])
      + 0.05400558f * (a1[1] + a1[5]) + 0.00443305f * (a1[0] + a1[6]));
    y2[i2 * 256] = __float2half_rn(
        0.19967563f * a2[6] + 0.17621312f * (a2[5] + a2[7])
      + 0.12110939f * (a2[4] + a2[8]) + 0.06482519f * (a2[3] + a2[9])
      + 0.02702316f * (a2[2] + a2[10]) + 0.00877314f * (a2[1] + a2[11])
      + 0.00221820f * (a2[0] + a2[12]));
    #pragma unroll
    for (int d = 0; d < 12; d++) a2[d] = a2[d + 1];
    #pragma unroll
    for (int d = 0; d < 6; d++) a1[d] = a1[d + 1];
    a0[0] = a0[1]; a0[1] = a0[2];
  }
}

// ---------------------------------------------------------------------------
// Kernel 2: fused 1x1 conv via mma.sync m16n8k16 fp16 (fp32 accum) + bias +
// residual.  CTA = 128 px x 64 o; 2 CTA/SM (77 KB smem, <=128 regs).
// A: fp16 y tile staged [k][px] via cp.async (pure 16B copies), consumed by
// ldmatrix.x4.trans; 136-half padded stride => conflict-free 8-row tiles.
// B: fragment-order half2 pairs (one LDS.64 per frag). 12 k-steps of k16.
// ---------------------------------------------------------------------------
#define SA_STRH 136                        // halfs per k-row (272 B)
#define SMH_B   52224                      // 192*136*2
#define SMH_FB  76800                      // + 12*8*32*8
#define SMH_TOT 77056

__global__ __launch_bounds__(256, 2) void fuse_mma_kernel(
    const float* __restrict__ x, const float* __restrict__ wf,
    const float* __restrict__ fb, float* __restrict__ out) {
  extern __shared__ char smc[];
  __half* sA = (__half*)smc;               // [192][136] half
  uint2* sB = (uint2*)(smc + SMH_B);       // [12][8][32] {k01, k89} half2 pairs
  float* sFB = (float*)(smc + SMH_FB);
  const uint32_t smbA = smem_u32(smc);

  const int t = threadIdx.x;
  const int lane = t & 31, w = t >> 5;
  const int g = lane >> 2, cc = lane & 3;
  const int b = blockIdx.x >> 9;
  const int px0 = (blockIdx.x & 511) << 7;

  if (t < 64) sFB[t] = fb[t];

  // A: cp.async 16B chunks, [k][px] natural layout, padded stride
  const __half* yb = g_v + (size_t)b * 192 * 65536 + px0;
  #pragma unroll
  for (int i = 0; i < 12; i++) {
    const int idx = i * 256 + t;
    const int k = idx >> 4, c = idx & 15;       // 192 rows x 16 chunks
    const uint32_t dst = smbA + k * 272 + c * 16;
    const __half* src = yb + (size_t)k * 65536 + c * 8;
    asm volatile("cp.async.cg.shared.global [%0], [%1], 16;"
                 :: "r"(dst), "l"(src));
  }
  asm volatile("cp.async.commit_group;");

  // B fragments: sB[kk*256 + j*32 + lane] = {W[o][kb+2c..+1], W[o][kb+2c+8..+9]}
  #pragma unroll
  for (int i = 0; i < 12; i++) {
    const int idx = i * 256 + t;
    const int kk = idx >> 8, rem = idx & 255;
    const int jj = rem >> 5, ln = rem & 31;
    const int o = (jj << 3) + (ln >> 2), kb = (kk << 4) + ((ln & 3) << 1);
    const float* wp = wf + o * 192 + kb;
    __half2 p0 = __floats2half2_rn(wp[0], wp[1]);
    __half2 p1 = __floats2half2_rn(wp[8], wp[9]);
    sB[idx] = make_uint2(*(uint32_t*)&p0, *(uint32_t*)&p1);
  }

  asm volatile("cp.async.wait_group 0;");
  __syncthreads();

  // ldmatrix lane address: tile order a0(mL,kL) a1(mH,kL) a2(mL,kH) a3(mH,kH)
  const int row8 = lane & 7;
  const int px_add = ((lane >> 3) & 1) << 3;
  const int k_add = (lane >> 4) << 3;
  uint32_t a_addr = smbA + ((k_add + row8) * SA_STRH + (w << 4) + px_add) * 2;

  float acc[8][4];
  #pragma unroll
  for (int j = 0; j < 8; j++)
    #pragma unroll
    for (int q = 0; q < 4; q++) acc[j][q] = 0.f;

  #pragma unroll
  for (int kk = 0; kk < 12; kk++) {
    uint32_t a0, a1, a2, a3;
    asm volatile(
        "ldmatrix.sync.aligned.m8n8.x4.trans.shared.b16 {%0,%1,%2,%3}, [%4];"
        : "=r"(a0), "=r"(a1), "=r"(a2), "=r"(a3) : "r"(a_addr));
    a_addr += 16 * SA_STRH * 2;
    const uint2* bp = sB + (kk << 8) + lane;
    #pragma unroll
    for (int j = 0; j < 8; j++) {
      const uint2 bv = bp[j << 5];
      asm volatile(
          "mma.sync.aligned.m16n8k16.row.col.f32.f16.f16.f32 "
          "{%0,%1,%2,%3}, {%4,%5,%6,%7}, {%8,%9}, {%0,%1,%2,%3};"
          : "+f"(acc[j][0]), "+f"(acc[j][1]), "+f"(acc[j][2]), "+f"(acc[j][3])
          : "r"(a0), "r"(a1), "r"(a2), "r"(a3), "r"(bv.x), "r"(bv.y));
    }
  }

  // epilogue: thread holds rows pxg, pxg+8; cols o0=8j+2c, o1=o0+1
  const int pxg = px0 + (w << 4) + g;
  const size_t bb = (size_t)(b << 6) * 65536;
  #pragma unroll
  for (int j = 0; j < 8; j++) {
    const int o0 = (j << 3) + (cc << 1), o1 = o0 + 1;
    const float fb0 = sFB[o0], fb1 = sFB[o1];
    const size_t a0i = bb + (size_t)o0 * 65536 + pxg;
    const size_t a1i = bb + (size_t)o1 * 65536 + pxg;
    out[a0i]     = x[a0i]     + fb0 + acc[j][0];
    out[a1i]     = x[a1i]     + fb1 + acc[j][1];
    out[a0i + 8] = x[a0i + 8] + fb0 + acc[j][2];
    out[a1i + 8] = x[a1i + 8] + fb1 + acc[j][3];
  }
}

// ---------------------------------------------------------------------------
extern "C" void kernel_launch(void* const* d_in, const int* in_sizes, int n_in,
                              void* d_out, int out_size) {
  const float* x  = (const float*)d_in[0];   // [8,64,256,256] f32
  const float* wf = (const float*)d_in[1];   // [64,192] f32
  const float* fb = (const float*)d_in[2];   // [64] f32
  float* out = (float*)d_out;                // [8,64,256,256] f32

  cudaFuncSetAttribute(blur_kernel,
                       cudaFuncAttributeMaxDynamicSharedMemorySize, 81776);
  blur_kernel<<<dim3(4, 4, 512), 256, 81776>>>(x);

  cudaFuncSetAttribute(fuse_mma_kernel,
                       cudaFuncAttributeMaxDynamicSharedMemorySize, SMH_TOT);
  fuse_mma_kernel<<<4096, 256, SMH_TOT>>>(x, wf, fb, out);
}

// round 12
// speedup vs baseline: 3.6076x; 1.0724x over previous
#include <cuda_runtime.h>
#include <cuda_fp16.h>
#include <cstdint>

// scratch: y[b][s*64+c][h][w] = Blur_s(x[b][c])  fp16 (8*192*256*256 = 192 MB)
__device__ __half g_v[100663296];

__device__ __forceinline__ uint32_t smem_u32(const void* p) {
  uint32_t a;
  asm("{ .reg .u64 t; cvta.to.shared.u64 t, %1; cvt.u32.u64 %0, t; }"
      : "=r"(a) : "l"(p));
  return a;
}

// ---------------------------------------------------------------------------
// Kernel 1: separable 3-scale blur. fp16 hb intermediate (smem 52.6 KB ->
// 4 CTA/SM), column-pair vertical pass with packed half2 stores.
// ---------------------------------------------------------------------------
__global__ __launch_bounds__(256) void blur_kernel(const float* __restrict__ x) {
  extern __shared__ float sm[];
  float* sv = sm;                          // [76][77] raw x tile (+halo)
  __half2* hb = (__half2*)(sm + 5852);     // [3][76][32] col-pairs (29184 B)

  const int t = threadIdx.x;
  const int pl = blockIdx.z;    // b*64 + c
  const int b = pl >> 6, c = pl & 63;
  const int h0 = blockIdx.y << 6, w0 = blockIdx.x << 6;
  const float* xp = x + (size_t)pl * 65536;

  for (int i = t; i < 5776; i += 256) {
    const int r = i / 76, cc = i - r * 76;
    const int hh = h0 - 6 + r, ww = w0 - 6 + cc;
    float v = 0.f;
    if ((unsigned)hh < 256u && (unsigned)ww < 256u) v = xp[hh * 256 + ww];
    sv[r * 77 + cc] = v;
  }
  __syncthreads();

  // horizontal: 76 rows x 32 col-pairs; 14 shared reads feed 2 cols x 3 scales
  for (int i = t; i < 2432; i += 256) {
    const int r = i >> 5, jp = i & 31;
    const float* p = sv + r * 77 + (jp << 1);
    float v[14];
    #pragma unroll
    for (int q = 0; q < 14; q++) v[q] = p[q];
    const float h0a = 0.78698604f * v[6] + 0.10650698f * (v[5] + v[7]);
    const float h0b = 0.78698604f * v[7] + 0.10650698f * (v[6] + v[8]);
    const float h1a = 0.39905028f * v[6] + 0.24203623f * (v[5] + v[7])
                    + 0.05400558f * (v[4] + v[8]) + 0.00443305f * (v[3] + v[9]);
    const float h1b = 0.39905028f * v[7] + 0.24203623f * (v[6] + v[8])
                    + 0.05400558f * (v[5] + v[9]) + 0.00443305f * (v[4] + v[10]);
    const float h2a = 0.19967563f * v[6] + 0.17621312f * (v[5] + v[7])
                    + 0.12110939f * (v[4] + v[8]) + 0.06482519f * (v[3] + v[9])
                    + 0.02702316f * (v[2] + v[10]) + 0.00877314f * (v[1] + v[11])
                    + 0.00221820f * (v[0] + v[12]);
    const float h2b = 0.19967563f * v[7] + 0.17621312f * (v[6] + v[8])
                    + 0.12110939f * (v[5] + v[9]) + 0.06482519f * (v[4] + v[10])
                    + 0.02702316f * (v[3] + v[11]) + 0.00877314f * (v[2] + v[12])
                    + 0.00221820f * (v[1] + v[13]);
    hb[(0 * 76 + r) * 32 + jp] = __floats2half2_rn(h0a, h0b);
    hb[(1 * 76 + r) * 32 + jp] = __floats2half2_rn(h1a, h1b);
    hb[(2 * 76 + r) * 32 + jp] = __floats2half2_rn(h2a, h2b);
  }
  __syncthreads();

  // vertical: thread = (col-pair jp, 8-row group rg); register-sliding float2
  const int jp = t & 31, rg = t >> 5;
  const int base = rg << 3;
  const int pr2 = (w0 >> 1) + jp;          // half2 col index in 128-wide row
  __half2* y0 = (__half2*)(g_v + (size_t)(b * 192 + c) * 65536);
  __half2* y1 = (__half2*)(g_v + (size_t)(b * 192 + 64 + c) * 65536);
  __half2* y2 = (__half2*)(g_v + (size_t)(b * 192 + 128 + c) * 65536);

  float2 a2[13], a1[7], a0[3];
  #pragma unroll
  for (int d = 0; d < 12; d++) a2[d] = __half22float2(hb[(2 * 76 + base + d) * 32 + jp]);
  #pragma unroll
  for (int d = 0; d < 6; d++) a1[d] = __half22float2(hb[(1 * 76 + base + 3 + d) * 32 + jp]);
  a0[0] = __half22float2(hb[(0 * 76 + base + 5) * 32 + jp]);
  a0[1] = __half22float2(hb[(0 * 76 + base + 6) * 32 + jp]);

  #pragma unroll
  for (int i2 = 0; i2 < 8; i2++) {
    a2[12] = __half22float2(hb[(2 * 76 + base + i2 + 12) * 32 + jp]);
    a1[6]  = __half22float2(hb[(1 * 76 + base + i2 + 9) * 32 + jp]);
    a0[2]  = __half22float2(hb[(0 * 76 + base + i2 + 7) * 32 + jp]);
    const int row = (h0 + base + i2) * 128 + pr2;
    float rx, ry;
    rx = 0.78698604f * a0[1].x + 0.10650698f * (a0[0].x + a0[2].x);
    ry = 0.78698604f * a0[1].y + 0.10650698f * (a0[0].y + a0[2].y);
    y0[row] = __floats2half2_rn(rx, ry);
    rx = 0.39905028f * a1[3].x + 0.24203623f * (a1[2].x + a1[4].x)
       + 0.05400558f * (a1[1].x + a1[5].x) + 0.00443305f * (a1[0].x + a1[6].x);
    ry = 0.39905028f * a1[3].y + 0.24203623f * (a1[2].y + a1[4].y)
       + 0.05400558f * (a1[1].y + a1[5].y) + 0.00443305f * (a1[0].y + a1[6].y);
    y1[row] = __floats2half2_rn(rx, ry);
    rx = 0.19967563f * a2[6].x + 0.17621312f * (a2[5].x + a2[7].x)
       + 0.12110939f * (a2[4].x + a2[8].x) + 0.06482519f * (a2[3].x + a2[9].x)
       + 0.02702316f * (a2[2].x + a2[10].x) + 0.00877314f * (a2[1].x + a2[11].x)
       + 0.00221820f * (a2[0].x + a2[12].x);
    ry = 0.19967563f * a2[6].y + 0.17621312f * (a2[5].y + a2[7].y)
       + 0.12110939f * (a2[4].y + a2[8].y) + 0.06482519f * (a2[3].y + a2[9].y)
       + 0.02702316f * (a2[2].y + a2[10].y) + 0.00877314f * (a2[1].y + a2[11].y)
       + 0.00221820f * (a2[0].y + a2[12].y);
    y2[row] = __floats2half2_rn(rx, ry);
    #pragma unroll
    for (int d = 0; d < 12; d++) a2[d] = a2[d + 1];
    #pragma unroll
    for (int d = 0; d < 6; d++) a1[d] = a1[d + 1];
    a0[0] = a0[1]; a0[1] = a0[2];
  }
}

// ---------------------------------------------------------------------------
// Kernel 2: fused 1x1 conv via mma.sync m16n8k16 fp16 + bias + residual.
// CTA = 64 px x 64 o, 128 threads, 52.5 KB smem -> 4 CTA/SM (phase overlap).
// Same proven frag mappings as R11; A stride 72 halfs (4-bank row skew,
// conflict-free ldmatrix).
// ---------------------------------------------------------------------------
#define SA_STRH 72                         // halfs per k-row (144 B)
#define SMH_B   27648                      // 192*72*2
#define SMH_FB  52224                      // + 12*8*32*8
#define SMH_TOT 52480

__global__ __launch_bounds__(128, 4) void fuse_mma_kernel(
    const float* __restrict__ x, const float* __restrict__ wf,
    const float* __restrict__ fb, float* __restrict__ out) {
  extern __shared__ char smc[];
  uint2* sB = (uint2*)(smc + SMH_B);       // [12][8][32] {k01, k89} half2 pairs
  float* sFB = (float*)(smc + SMH_FB);
  const uint32_t smbA = smem_u32(smc);

  const int t = threadIdx.x;
  const int lane = t & 31, w = t >> 5;
  const int g = lane >> 2, cc = lane & 3;
  const int b = blockIdx.x >> 10;
  const int px0 = (blockIdx.x & 1023) << 6;

  if (t < 64) sFB[t] = fb[t];

  // A: cp.async 16B chunks, [k][px] layout, 64 halfs/row + pad
  const __half* yb = g_v + (size_t)b * 192 * 65536 + px0;
  #pragma unroll
  for (int i = 0; i < 12; i++) {
    const int idx = i * 128 + t;
    const int k = idx >> 3, c = idx & 7;        // 192 rows x 8 chunks
    const uint32_t dst = smbA + k * 144 + c * 16;
    const __half* src = yb + (size_t)k * 65536 + c * 8;
    asm volatile("cp.async.cg.shared.global [%0], [%1], 16;"
                 :: "r"(dst), "l"(src));
  }
  asm volatile("cp.async.commit_group;");

  // B fragments: sB[kk*256 + j*32 + lane] = {W[o][kb..kb+1], W[o][kb+8..+9]}
  #pragma unroll
  for (int i = 0; i < 24; i++) {
    const int idx = i * 128 + t;
    const int kk = idx >> 8, rem = idx & 255;
    const int jj = rem >> 5, ln = rem & 31;
    const int o = (jj << 3) + (ln >> 2), kb = (kk << 4) + ((ln & 3) << 1);
    const float* wp = wf + o * 192 + kb;
    __half2 p0 = __floats2half2_rn(wp[0], wp[1]);
    __half2 p1 = __floats2half2_rn(wp[8], wp[9]);
    sB[idx] = make_uint2(*(uint32_t*)&p0, *(uint32_t*)&p1);
  }

  asm volatile("cp.async.wait_group 0;");
  __syncthreads();

  // ldmatrix: a0(mL,kL) a1(mH,kL) a2(mL,kH) a3(mH,kH)
  const int row8 = lane & 7;
  const int px_add = ((lane >> 3) & 1) << 3;
  const int k_add = (lane >> 4) << 3;
  uint32_t a_addr = smbA + ((k_add + row8) * SA_STRH + (w << 4) + px_add) * 2;

  float acc[8][4];
  #pragma unroll
  for (int j = 0; j < 8; j++)
    #pragma unroll
    for (int q = 0; q < 4; q++) acc[j][q] = 0.f;

  #pragma unroll
  for (int kk = 0; kk < 12; kk++) {
    uint32_t a0, a1, a2, a3;
    asm volatile(
        "ldmatrix.sync.aligned.m8n8.x4.trans.shared.b16 {%0,%1,%2,%3}, [%4];"
        : "=r"(a0), "=r"(a1), "=r"(a2), "=r"(a3) : "r"(a_addr));
    a_addr += 16 * SA_STRH * 2;
    const uint2* bp = sB + (kk << 8) + lane;
    #pragma unroll
    for (int j = 0; j < 8; j++) {
      const uint2 bv = bp[j << 5];
      asm volatile(
          "mma.sync.aligned.m16n8k16.row.col.f32.f16.f16.f32 "
          "{%0,%1,%2,%3}, {%4,%5,%6,%7}, {%8,%9}, {%0,%1,%2,%3};"
          : "+f"(acc[j][0]), "+f"(acc[j][1]), "+f"(acc[j][2]), "+f"(acc[j][3])
          : "r"(a0), "r"(a1), "r"(a2), "r"(a3), "r"(bv.x), "r"(bv.y));
    }
  }

  // epilogue: thread holds rows pxg, pxg+8; cols o0=8j+2c, o1=o0+1
  const int pxg = px0 + (w << 4) + g;
  const size_t bb = (size_t)(b << 6) * 65536;
  #pragma unroll
  for (int j = 0; j < 8; j++) {
    const int o0 = (j << 3) + (cc << 1), o1 = o0 + 1;
    const float fb0 = sFB[o0], fb1 = sFB[o1];
    const size_t a0i = bb + (size_t)o0 * 65536 + pxg;
    const size_t a1i = bb + (size_t)o1 * 65536 + pxg;
    out[a0i]     = x[a0i]     + fb0 + acc[j][0];
    out[a1i]     = x[a1i]     + fb1 + acc[j][1];
    out[a0i + 8] = x[a0i + 8] + fb0 + acc[j][2];
    out[a1i + 8] = x[a1i + 8] + fb1 + acc[j][3];
  }
}

// ---------------------------------------------------------------------------
extern "C" void kernel_launch(void* const* d_in, const int* in_sizes, int n_in,
                              void* d_out, int out_size) {
  const float* x  = (const float*)d_in[0];   // [8,64,256,256] f32
  const float* wf = (const float*)d_in[1];   // [64,192] f32
  const float* fb = (const float*)d_in[2];   // [64] f32
  float* out = (float*)d_out;                // [8,64,256,256] f32

  cudaFuncSetAttribute(blur_kernel,
                       cudaFuncAttributeMaxDynamicSharedMemorySize, 52592);
  blur_kernel<<<dim3(4, 4, 512), 256, 52592>>>(x);

  cudaFuncSetAttribute(fuse_mma_kernel,
                       cudaFuncAttributeMaxDynamicSharedMemorySize, SMH_TOT);
  fuse_mma_kernel<<<8192, 128, SMH_TOT>>>(x, wf, fb, out);
}

// round 13
// speedup vs baseline: 4.9496x; 1.3720x over previous
#include <cuda_runtime.h>
#include <cuda_fp16.h>
#include <cstdint>

// scratch: y[b][s*64+c][h][w] = Blur_s(x[b][c])  fp16 (8*192*256*256 = 192 MB)
__device__ __half g_v[100663296];

__device__ __forceinline__ uint32_t smem_u32(const void* p) {
  uint32_t a;
  asm("{ .reg .u64 t; cvta.to.shared.u64 t, %1; cvt.u32.u64 %0, t; }"
      : "=r"(a) : "l"(p));
  return a;
}

// ---------------------------------------------------------------------------
// Kernel 1: separable 3-scale blur (R12-proven: fp16 hb, 4 CTA/SM).
// ---------------------------------------------------------------------------
__global__ __launch_bounds__(256) void blur_kernel(const float* __restrict__ x) {
  extern __shared__ float sm[];
  float* sv = sm;                          // [76][77] raw x tile (+halo)
  __half2* hb = (__half2*)(sm + 5852);     // [3][76][32] col-pairs

  const int t = threadIdx.x;
  const int pl = blockIdx.z;    // b*64 + c
  const int b = pl >> 6, c = pl & 63;
  const int h0 = blockIdx.y << 6, w0 = blockIdx.x << 6;
  const float* xp = x + (size_t)pl * 65536;

  for (int i = t; i < 5776; i += 256) {
    const int r = i / 76, cc = i - r * 76;
    const int hh = h0 - 6 + r, ww = w0 - 6 + cc;
    float v = 0.f;
    if ((unsigned)hh < 256u && (unsigned)ww < 256u) v = xp[hh * 256 + ww];
    sv[r * 77 + cc] = v;
  }
  __syncthreads();

  for (int i = t; i < 2432; i += 256) {
    const int r = i >> 5, jp = i & 31;
    const float* p = sv + r * 77 + (jp << 1);
    float v[14];
    #pragma unroll
    for (int q = 0; q < 14; q++) v[q] = p[q];
    const float h0a = 0.78698604f * v[6] + 0.10650698f * (v[5] + v[7]);
    const float h0b = 0.78698604f * v[7] + 0.10650698f * (v[6] + v[8]);
    const float h1a = 0.39905028f * v[6] + 0.24203623f * (v[5] + v[7])
                    + 0.05400558f * (v[4] + v[8]) + 0.00443305f * (v[3] + v[9]);
    const float h1b = 0.39905028f * v[7] + 0.24203623f * (v[6] + v[8])
                    + 0.05400558f * (v[5] + v[9]) + 0.00443305f * (v[4] + v[10]);
    const float h2a = 0.19967563f * v[6] + 0.17621312f * (v[5] + v[7])
                    + 0.12110939f * (v[4] + v[8]) + 0.06482519f * (v[3] + v[9])
                    + 0.02702316f * (v[2] + v[10]) + 0.00877314f * (v[1] + v[11])
                    + 0.00221820f * (v[0] + v[12]);
    const float h2b = 0.19967563f * v[7] + 0.17621312f * (v[6] + v[8])
                    + 0.12110939f * (v[5] + v[9]) + 0.06482519f * (v[4] + v[10])
                    + 0.02702316f * (v[3] + v[11]) + 0.00877314f * (v[2] + v[12])
                    + 0.00221820f * (v[1] + v[13]);
    hb[(0 * 76 + r) * 32 + jp] = __floats2half2_rn(h0a, h0b);
    hb[(1 * 76 + r) * 32 + jp] = __floats2half2_rn(h1a, h1b);
    hb[(2 * 76 + r) * 32 + jp] = __floats2half2_rn(h2a, h2b);
  }
  __syncthreads();

  const int jp = t & 31, rg = t >> 5;
  const int base = rg << 3;
  const int pr2 = (w0 >> 1) + jp;
  __half2* y0 = (__half2*)(g_v + (size_t)(b * 192 + c) * 65536);
  __half2* y1 = (__half2*)(g_v + (size_t)(b * 192 + 64 + c) * 65536);
  __half2* y2 = (__half2*)(g_v + (size_t)(b * 192 + 128 + c) * 65536);

  float2 a2[13], a1[7], a0[3];
  #pragma unroll
  for (int d = 0; d < 12; d++) a2[d] = __half22float2(hb[(2 * 76 + base + d) * 32 + jp]);
  #pragma unroll
  for (int d = 0; d < 6; d++) a1[d] = __half22float2(hb[(1 * 76 + base + 3 + d) * 32 + jp]);
  a0[0] = __half22float2(hb[(0 * 76 + base + 5) * 32 + jp]);
  a0[1] = __half22float2(hb[(0 * 76 + base + 6) * 32 + jp]);

  #pragma unroll
  for (int i2 = 0; i2 < 8; i2++) {
    a2[12] = __half22float2(hb[(2 * 76 + base + i2 + 12) * 32 + jp]);
    a1[6]  = __half22float2(hb[(1 * 76 + base + i2 + 9) * 32 + jp]);
    a0[2]  = __half22float2(hb[(0 * 76 + base + i2 + 7) * 32 + jp]);
    const int row = (h0 + base + i2) * 128 + pr2;
    float rx, ry;
    rx = 0.78698604f * a0[1].x + 0.10650698f * (a0[0].x + a0[2].x);
    ry = 0.78698604f * a0[1].y + 0.10650698f * (a0[0].y + a0[2].y);
    y0[row] = __floats2half2_rn(rx, ry);
    rx = 0.39905028f * a1[3].x + 0.24203623f * (a1[2].x + a1[4].x)
       + 0.05400558f * (a1[1].x + a1[5].x) + 0.00443305f * (a1[0].x + a1[6].x);
    ry = 0.39905028f * a1[3].y + 0.24203623f * (a1[2].y + a1[4].y)
       + 0.05400558f * (a1[1].y + a1[5].y) + 0.00443305f * (a1[0].y + a1[6].y);
    y1[row] = __floats2half2_rn(rx, ry);
    rx = 0.19967563f * a2[6].x + 0.17621312f * (a2[5].x + a2[7].x)
       + 0.12110939f * (a2[4].x + a2[8].x) + 0.06482519f * (a2[3].x + a2[9].x)
       + 0.02702316f * (a2[2].x + a2[10].x) + 0.00877314f * (a2[1].x + a2[11].x)
       + 0.00221820f * (a2[0].x + a2[12].x);
    ry = 0.19967563f * a2[6].y + 0.17621312f * (a2[5].y + a2[7].y)
       + 0.12110939f * (a2[4].y + a2[8].y) + 0.06482519f * (a2[3].y + a2[9].y)
       + 0.02702316f * (a2[2].y + a2[10].y) + 0.00877314f * (a2[1].y + a2[11].y)
       + 0.00221820f * (a2[0].y + a2[12].y);
    y2[row] = __floats2half2_rn(rx, ry);
    #pragma unroll
    for (int d = 0; d < 12; d++) a2[d] = a2[d + 1];
    #pragma unroll
    for (int d = 0; d < 6; d++) a1[d] = a1[d + 1];
    a0[0] = a0[1]; a0[1] = a0[2];
  }
}

// ---------------------------------------------------------------------------
// Kernel 2: persistent fused 1x1 conv via mma.sync m16n8k16 fp16 + bias +
// residual.  296 CTAs (2/SM), 256 thr, ~14 tiles of 128 px each.
// B fragments + bias staged ONCE per CTA; A single-buffered with cross-tile
// overlap: next tile's cp.async issues before the current epilogue, so the
// DMA runs under the epilogue's long-latency LDG/STG.
// ---------------------------------------------------------------------------
#define SA_STRH 136                        // halfs per k-row (272 B)
#define SMH_B   52224                      // 192*136*2
#define SMH_FB  76800                      // + 12*8*32*8
#define SMH_TOT 77056
#define NTILES  4096
#define NCTA    296

__global__ __launch_bounds__(256, 2) void fuse_mma_kernel(
    const float* __restrict__ x, const float* __restrict__ wf,
    const float* __restrict__ fb, float* __restrict__ out) {
  extern __shared__ char smc[];
  uint2* sB = (uint2*)(smc + SMH_B);       // [12][8][32] {k01, k89} half2 pairs
  float* sFB = (float*)(smc + SMH_FB);
  const uint32_t smbA = smem_u32(smc);

  const int t = threadIdx.x;
  const int lane = t & 31, w = t >> 5;
  const int g = lane >> 2, cc = lane & 3;

  if (t < 64) sFB[t] = fb[t];

  // B fragments once per CTA: sB[kk*256+j*32+lane] = {W[o][kb..+1], W[o][kb+8..+9]}
  #pragma unroll
  for (int i = 0; i < 12; i++) {
    const int idx = i * 256 + t;
    const int kk = idx >> 8, rem = idx & 255;
    const int jj = rem >> 5, ln = rem & 31;
    const int o = (jj << 3) + (ln >> 2), kb = (kk << 4) + ((ln & 3) << 1);
    const float* wp = wf + o * 192 + kb;
    __half2 p0 = __floats2half2_rn(wp[0], wp[1]);
    __half2 p1 = __floats2half2_rn(wp[8], wp[9]);
    sB[idx] = make_uint2(*(uint32_t*)&p0, *(uint32_t*)&p1);
  }

  // prefetch A for first tile
  {
    const int tile = blockIdx.x;
    const __half* yb = g_v + ((size_t)(tile >> 9) * 192 * 65536) +
                       ((tile & 511) << 7);
    #pragma unroll
    for (int i = 0; i < 12; i++) {
      const int idx = i * 256 + t;
      const int k = idx >> 4, c = idx & 15;
      const uint32_t dst = smbA + k * 272 + c * 16;
      asm volatile("cp.async.cg.shared.global [%0], [%1], 16;"
                   :: "r"(dst), "l"(yb + (size_t)k * 65536 + c * 8));
    }
    asm volatile("cp.async.commit_group;");
  }

  // ldmatrix lane address: a0(mL,kL) a1(mH,kL) a2(mL,kH) a3(mH,kH)
  const int row8 = lane & 7;
  const int px_add = ((lane >> 3) & 1) << 3;
  const int k_add = (lane >> 4) << 3;
  const uint32_t a_addr0 =
      smbA + ((k_add + row8) * SA_STRH + (w << 4) + px_add) * 2;

  for (int tile = blockIdx.x; tile < NTILES; tile += NCTA) {
    const int b = tile >> 9;
    const int px0 = (tile & 511) << 7;

    asm volatile("cp.async.wait_group 0;");
    __syncthreads();

    float acc[8][4];
    #pragma unroll
    for (int j = 0; j < 8; j++)
      #pragma unroll
      for (int q = 0; q < 4; q++) acc[j][q] = 0.f;

    uint32_t a_addr = a_addr0;
    #pragma unroll
    for (int kk = 0; kk < 12; kk++) {
      uint32_t a0, a1, a2, a3;
      asm volatile(
          "ldmatrix.sync.aligned.m8n8.x4.trans.shared.b16 {%0,%1,%2,%3}, [%4];"
          : "=r"(a0), "=r"(a1), "=r"(a2), "=r"(a3) : "r"(a_addr));
      a_addr += 16 * SA_STRH * 2;
      const uint2* bp = sB + (kk << 8) + lane;
      #pragma unroll
      for (int j = 0; j < 8; j++) {
        const uint2 bv = bp[j << 5];
        asm volatile(
            "mma.sync.aligned.m16n8k16.row.col.f32.f16.f16.f32 "
            "{%0,%1,%2,%3}, {%4,%5,%6,%7}, {%8,%9}, {%0,%1,%2,%3};"
            : "+f"(acc[j][0]), "+f"(acc[j][1]), "+f"(acc[j][2]), "+f"(acc[j][3])
            : "r"(a0), "r"(a1), "r"(a2), "r"(a3), "r"(bv.x), "r"(bv.y));
      }
    }

    __syncthreads();   // all warps done reading sA

    // prefetch next tile's A — DMA overlaps the epilogue below
    const int ntile = tile + NCTA;
    if (ntile < NTILES) {
      const __half* yb = g_v + ((size_t)(ntile >> 9) * 192 * 65536) +
                         ((ntile & 511) << 7);
      #pragma unroll
      for (int i = 0; i < 12; i++) {
        const int idx = i * 256 + t;
        const int k = idx >> 4, c = idx & 15;
        const uint32_t dst = smbA + k * 272 + c * 16;
        asm volatile("cp.async.cg.shared.global [%0], [%1], 16;"
                     :: "r"(dst), "l"(yb + (size_t)k * 65536 + c * 8));
      }
    }
    asm volatile("cp.async.commit_group;");

    // epilogue: thread holds rows pxg, pxg+8; cols o0=8j+2c, o1=o0+1
    const int pxg = px0 + (w << 4) + g;
    const size_t bb = (size_t)(b << 6) * 65536;
    #pragma unroll
    for (int j = 0; j < 8; j++) {
      const int o0 = (j << 3) + (cc << 1), o1 = o0 + 1;
      const float fb0 = sFB[o0], fb1 = sFB[o1];
      const size_t a0i = bb + (size_t)o0 * 65536 + pxg;
      const size_t a1i = bb + (size_t)o1 * 65536 + pxg;
      out[a0i]     = x[a0i]     + fb0 + acc[j][0];
      out[a1i]     = x[a1i]     + fb1 + acc[j][1];
      out[a0i + 8] = x[a0i + 8] + fb0 + acc[j][2];
      out[a1i + 8] = x[a1i + 8] + fb1 + acc[j][3];
    }
  }
}

// ---------------------------------------------------------------------------
extern "C" void kernel_launch(void* const* d_in, const int* in_sizes, int n_in,
                              void* d_out, int out_size) {
  const float* x  = (const float*)d_in[0];   // [8,64,256,256] f32
  const float* wf = (const float*)d_in[1];   // [64,192] f32
  const float* fb = (const float*)d_in[2];   // [64] f32
  float* out = (float*)d_out;                // [8,64,256,256] f32

  cudaFuncSetAttribute(blur_kernel,
                       cudaFuncAttributeMaxDynamicSharedMemorySize, 52592);
  blur_kernel<<<dim3(4, 4, 512), 256, 52592>>>(x);

  cudaFuncSetAttribute(fuse_mma_kernel,
                       cudaFuncAttributeMaxDynamicSharedMemorySize, SMH_TOT);
  fuse_mma_kernel<<<NCTA, 256, SMH_TOT>>>(x, wf, fb, out);
}

// round 16
// speedup vs baseline: 5.1332x; 1.0371x over previous
#include <cuda_runtime.h>
#include <cuda_fp16.h>
#include <cstdint>

// scratch: y[b][s*64+c][h][w] = Blur_s(x[b][c])  fp16 (8*192*256*256 = 192 MB)
__device__ __half g_v[100663296];

__device__ __forceinline__ uint32_t smem_u32(const void* p) {
  uint32_t a;
  asm("{ .reg .u64 t; cvta.to.shared.u64 t, %1; cvt.u32.u64 %0, t; }"
      : "=r"(a) : "l"(p));
  return a;
}
__device__ __forceinline__ uint32_t h2u(__half2 h) { return *(uint32_t*)&h; }

// ---------------------------------------------------------------------------
// Kernel 1: separable 3-scale blur. Raw tile stride 78 (EVEN -> float2-
// aligned rows). Horizontal pass: 4-column items fed by 8 aligned LDS.64;
// packed STS.64 stores. fp16 hb intermediate, 4 CTA/SM. Vertical register-
// sliding pass unchanged (proven).
// ---------------------------------------------------------------------------
__global__ __launch_bounds__(256) void blur_kernel(const float* __restrict__ x) {
  extern __shared__ float sm[];
  float* sv = sm;                          // [76][78] raw x tile (+halo)
  __half2* hb = (__half2*)(sm + 5928);     // [3][76][32] col-pairs

  const int t = threadIdx.x;
  const int pl = blockIdx.z;    // b*64 + c
  const int b = pl >> 6, c = pl & 63;
  const int h0 = blockIdx.y << 6, w0 = blockIdx.x << 6;
  const float* xp = x + (size_t)pl * 65536;

  for (int i = t; i < 5776; i += 256) {
    const int r = i / 76, cc = i - r * 76;
    const int hh = h0 - 6 + r, ww = w0 - 6 + cc;
    float v = 0.f;
    if ((unsigned)hh < 256u && (unsigned)ww < 256u) v = xp[hh * 256 + ww];
    sv[r * 78 + cc] = v;
  }
  __syncthreads();

  // horizontal: 76 rows x 16 col-quads; 8 LDS.64 feed 4 cols x 3 scales
  for (int i = t; i < 1216; i += 256) {
    const int r = i >> 4, jq = i & 15;
    const float2* p = (const float2*)(sv + r * 78 + (jq << 2));  // 8B-aligned
    float v[16];
    #pragma unroll
    for (int q = 0; q < 8; q++) {
      const float2 d = p[q];
      v[2 * q] = d.x; v[2 * q + 1] = d.y;
    }
    float h0v[4], h1v[4], h2v[4];
    #pragma unroll
    for (int cu = 0; cu < 4; cu++) {
      h0v[cu] = 0.78698604f * v[cu + 6] + 0.10650698f * (v[cu + 5] + v[cu + 7]);
      h1v[cu] = 0.39905028f * v[cu + 6] + 0.24203623f * (v[cu + 5] + v[cu + 7])
              + 0.05400558f * (v[cu + 4] + v[cu + 8])
              + 0.00443305f * (v[cu + 3] + v[cu + 9]);
      h2v[cu] = 0.19967563f * v[cu + 6] + 0.17621312f * (v[cu + 5] + v[cu + 7])
              + 0.12110939f * (v[cu + 4] + v[cu + 8])
              + 0.06482519f * (v[cu + 3] + v[cu + 9])
              + 0.02702316f * (v[cu + 2] + v[cu + 10])
              + 0.00877314f * (v[cu + 1] + v[cu + 11])
              + 0.00221820f * (v[cu + 0] + v[cu + 12]);
    }
    // pack 4 cols -> two half2, one STS.64 per scale (conflict-free)
    *(uint2*)&hb[(0 * 76 + r) * 32 + (jq << 1)] = make_uint2(
        h2u(__floats2half2_rn(h0v[0], h0v[1])),
        h2u(__floats2half2_rn(h0v[2], h0v[3])));
    *(uint2*)&hb[(1 * 76 + r) * 32 + (jq << 1)] = make_uint2(
        h2u(__floats2half2_rn(h1v[0], h1v[1])),
        h2u(__floats2half2_rn(h1v[2], h1v[3])));
    *(uint2*)&hb[(2 * 76 + r) * 32 + (jq << 1)] = make_uint2(
        h2u(__floats2half2_rn(h2v[0], h2v[1])),
        h2u(__floats2half2_rn(h2v[2], h2v[3])));
  }
  __syncthreads();

  // vertical: thread = (col-pair jp, 8-row group rg); register-sliding float2
  const int jp = t & 31, rg = t >> 5;
  const int base = rg << 3;
  const int pr2 = (w0 >> 1) + jp;
  __half2* y0 = (__half2*)(g_v + (size_t)(b * 192 + c) * 65536);
  __half2* y1 = (__half2*)(g_v + (size_t)(b * 192 + 64 + c) * 65536);
  __half2* y2 = (__half2*)(g_v + (size_t)(b * 192 + 128 + c) * 65536);

  float2 a2[13], a1[7], a0[3];
  #pragma unroll
  for (int d = 0; d < 12; d++) a2[d] = __half22float2(hb[(2 * 76 + base + d) * 32 + jp]);
  #pragma unroll
  for (int d = 0; d < 6; d++) a1[d] = __half22float2(hb[(1 * 76 + base + 3 + d) * 32 + jp]);
  a0[0] = __half22float2(hb[(0 * 76 + base + 5) * 32 + jp]);
  a0[1] = __half22float2(hb[(0 * 76 + base + 6) * 32 + jp]);

  #pragma unroll
  for (int i2 = 0; i2 < 8; i2++) {
    a2[12] = __half22float2(hb[(2 * 76 + base + i2 + 12) * 32 + jp]);
    a1[6]  = __half22float2(hb[(1 * 76 + base + i2 + 9) * 32 + jp]);
    a0[2]  = __half22float2(hb[(0 * 76 + base + i2 + 7) * 32 + jp]);
    const int row = (h0 + base + i2) * 128 + pr2;
    float rx, ry;
    rx = 0.78698604f * a0[1].x + 0.10650698f * (a0[0].x + a0[2].x);
    ry = 0.78698604f * a0[1].y + 0.10650698f * (a0[0].y + a0[2].y);
    y0[row] = __floats2half2_rn(rx, ry);
    rx = 0.39905028f * a1[3].x + 0.24203623f * (a1[2].x + a1[4].x)
       + 0.05400558f * (a1[1].x + a1[5].x) + 0.00443305f * (a1[0].x + a1[6].x);
    ry = 0.39905028f * a1[3].y + 0.24203623f * (a1[2].y + a1[4].y)
       + 0.05400558f * (a1[1].y + a1[5].y) + 0.00443305f * (a1[0].y + a1[6].y);
    y1[row] = __floats2half2_rn(rx, ry);
    rx = 0.19967563f * a2[6].x + 0.17621312f * (a2[5].x + a2[7].x)
       + 0.12110939f * (a2[4].x + a2[8].x) + 0.06482519f * (a2[3].x + a2[9].x)
       + 0.02702316f * (a2[2].x + a2[10].x) + 0.00877314f * (a2[1].x + a2[11].x)
       + 0.00221820f * (a2[0].x + a2[12].x);
    ry = 0.19967563f * a2[6].y + 0.17621312f * (a2[5].y + a2[7].y)
       + 0.12110939f * (a2[4].y + a2[8].y) + 0.06482519f * (a2[3].y + a2[9].y)
       + 0.02702316f * (a2[2].y + a2[10].y) + 0.00877314f * (a2[1].y + a2[11].y)
       + 0.00221820f * (a2[0].y + a2[12].y);
    y2[row] = __floats2half2_rn(rx, ry);
    #pragma unroll
    for (int d = 0; d < 12; d++) a2[d] = a2[d + 1];
    #pragma unroll
    for (int d = 0; d < 6; d++) a1[d] = a1[d + 1];
    a0[0] = a0[1]; a0[1] = a0[2];
  }
}

// ---------------------------------------------------------------------------
// Kernel 2: persistent fused 1x1 conv (R13-proven, unchanged).
// 296 CTAs (2/SM), B fragments staged once, A single-buffered with cross-tile
// cp.async overlap under the epilogue.
// ---------------------------------------------------------------------------
#define SA_STRH 136                        // halfs per k-row (272 B)
#define SMH_B   52224                      // 192*136*2
#define SMH_FB  76800                      // + 12*8*32*8
#define SMH_TOT 77056
#define NTILES  4096
#define NCTA    296

__global__ __launch_bounds__(256, 2) void fuse_mma_kernel(
    const float* __restrict__ x, const float* __restrict__ wf,
    const float* __restrict__ fb, float* __restrict__ out) {
  extern __shared__ char smc[];
  uint2* sB = (uint2*)(smc + SMH_B);       // [12][8][32] {k01, k89} half2 pairs
  float* sFB = (float*)(smc + SMH_FB);
  const uint32_t smbA = smem_u32(smc);

  const int t = threadIdx.x;
  const int lane = t & 31, w = t >> 5;
  const int g = lane >> 2, cc = lane & 3;

  if (t < 64) sFB[t] = fb[t];

  // B fragments once per CTA
  #pragma unroll
  for (int i = 0; i < 12; i++) {
    const int idx = i * 256 + t;
    const int kk = idx >> 8, rem = idx & 255;
    const int jj = rem >> 5, ln = rem & 31;
    const int o = (jj << 3) + (ln >> 2), kb = (kk << 4) + ((ln & 3) << 1);
    const float* wp = wf + o * 192 + kb;
    __half2 p0 = __floats2half2_rn(wp[0], wp[1]);
    __half2 p1 = __floats2half2_rn(wp[8], wp[9]);
    sB[idx] = make_uint2(h2u(p0), h2u(p1));
  }

  // prefetch A for first tile
  {
    const int tile = blockIdx.x;
    const __half* yb = g_v + ((size_t)(tile >> 9) * 192 * 65536) +
                       ((tile & 511) << 7);
    #pragma unroll
    for (int i = 0; i < 12; i++) {
      const int idx = i * 256 + t;
      const int k = idx >> 4, c = idx & 15;
      const uint32_t dst = smbA + k * 272 + c * 16;
      asm volatile("cp.async.cg.shared.global [%0], [%1], 16;"
                   :: "r"(dst), "l"(yb + (size_t)k * 65536 + c * 8));
    }
    asm volatile("cp.async.commit_group;");
  }

  const int row8 = lane & 7;
  const int px_add = ((lane >> 3) & 1) << 3;
  const int k_add = (lane >> 4) << 3;
  const uint32_t a_addr0 =
      smbA + ((k_add + row8) * SA_STRH + (w << 4) + px_add) * 2;

  for (int tile = blockIdx.x; tile < NTILES; tile += NCTA) {
    const int b = tile >> 9;
    const int px0 = (tile & 511) << 7;

    asm volatile("cp.async.wait_group 0;");
    __syncthreads();

    float acc[8][4];
    #pragma unroll
    for (int j = 0; j < 8; j++)
      #pragma unroll
      for (int q = 0; q < 4; q++) acc[j][q] = 0.f;

    uint32_t a_addr = a_addr0;
    #pragma unroll
    for (int kk = 0; kk < 12; kk++) {
      uint32_t a0, a1, a2, a3;
      asm volatile(
          "ldmatrix.sync.aligned.m8n8.x4.trans.shared.b16 {%0,%1,%2,%3}, [%4];"
          : "=r"(a0), "=r"(a1), "=r"(a2), "=r"(a3) : "r"(a_addr));
      a_addr += 16 * SA_STRH * 2;
      const uint2* bp = sB + (kk << 8) + lane;
      #pragma unroll
      for (int j = 0; j < 8; j++) {
        const uint2 bv = bp[j << 5];
        asm volatile(
            "mma.sync.aligned.m16n8k16.row.col.f32.f16.f16.f32 "
            "{%0,%1,%2,%3}, {%4,%5,%6,%7}, {%8,%9}, {%0,%1,%2,%3};"
            : "+f"(acc[j][0]), "+f"(acc[j][1]), "+f"(acc[j][2]), "+f"(acc[j][3])
            : "r"(a0), "r"(a1), "r"(a2), "r"(a3), "r"(bv.x), "r"(bv.y));
      }
    }

    __syncthreads();   // all warps done reading sA

    // prefetch next tile's A — DMA overlaps the epilogue below
    const int ntile = tile + NCTA;
    if (ntile < NTILES) {
      const __half* yb = g_v + ((size_t)(ntile >> 9) * 192 * 65536) +
                         ((ntile & 511) << 7);
      #pragma unroll
      for (int i = 0; i < 12; i++) {
        const int idx = i * 256 + t;
        const int k = idx >> 4, c = idx & 15;
        const uint32_t dst = smbA + k * 272 + c * 16;
        asm volatile("cp.async.cg.shared.global [%0], [%1], 16;"
                     :: "r"(dst), "l"(yb + (size_t)k * 65536 + c * 8));
      }
    }
    asm volatile("cp.async.commit_group;");

    // epilogue: thread holds rows pxg, pxg+8; cols o0=8j+2c, o1=o0+1
    const int pxg = px0 + (w << 4) + g;
    const size_t bb = (size_t)(b << 6) * 65536;
    #pragma unroll
    for (int j = 0; j < 8; j++) {
      const int o0 = (j << 3) + (cc << 1), o1 = o0 + 1;
      const float fb0 = sFB[o0], fb1 = sFB[o1];
      const size_t a0i = bb + (size_t)o0 * 65536 + pxg;
      const size_t a1i = bb + (size_t)o1 * 65536 + pxg;
      out[a0i]     = x[a0i]     + fb0 + acc[j][0];
      out[a1i]     = x[a1i]     + fb1 + acc[j][1];
      out[a0i + 8] = x[a0i + 8] + fb0 + acc[j][2];
      out[a1i + 8] = x[a1i + 8] + fb1 + acc[j][3];
    }
  }
}

// ---------------------------------------------------------------------------
extern "C" void kernel_launch(void* const* d_in, const int* in_sizes, int n_in,
                              void* d_out, int out_size) {
  const float* x  = (const float*)d_in[0];   // [8,64,256,256] f32
  const float* wf = (const float*)d_in[1];   // [64,192] f32
  const float* fb = (const float*)d_in[2];   // [64] f32
  float* out = (float*)d_out;                // [8,64,256,256] f32

  cudaFuncSetAttribute(blur_kernel,
                       cudaFuncAttributeMaxDynamicSharedMemorySize, 52896);
  blur_kernel<<<dim3(4, 4, 512), 256, 52896>>>(x);

  cudaFuncSetAttribute(fuse_mma_kernel,
                       cudaFuncAttributeMaxDynamicSharedMemorySize, SMH_TOT);
  fuse_mma_kernel<<<NCTA, 256, SMH_TOT>>>(x, wf, fb, out);
}

// round 17
// speedup vs baseline: 6.0347x; 1.1756x over previous
#include <cuda_runtime.h>
#include <cuda_fp16.h>
#include <cstdint>

// scratch: y[b][s*64+c][h][w] = Blur_s(x[b][c])  fp16 (8*192*256*256 = 192 MB)
__device__ __half g_v[100663296];

__device__ __forceinline__ uint32_t smem_u32(const void* p) {
  uint32_t a;
  asm("{ .reg .u64 t; cvta.to.shared.u64 t, %1; cvt.u32.u64 %0, t; }"
      : "=r"(a) : "l"(p));
  return a;
}
__device__ __forceinline__ uint32_t h2u(__half2 h) { return *(uint32_t*)&h; }
__device__ __forceinline__ __half2 u2h(uint32_t u) { return *(__half2*)&u; }

// ---------------------------------------------------------------------------
// Kernel 1: separable 3-scale blur, full half2 SIMD (2 cols/instr).
// sv staged as fp16 (12.2 KB); horizontal: 4 LDS.64 + 7 PRMT build the
// even/odd-shifted half2 streams, symmetric HADD2s shared across scales;
// vertical: half2 register-sliding windows, direct half2 stores (no cvt).
// smem 41.3 KB -> 4+ CTA/SM.
// ---------------------------------------------------------------------------
__global__ __launch_bounds__(256) void blur_kernel(const float* __restrict__ x) {
  extern __shared__ float sm[];
  __half* sv = (__half*)sm;                // [76][80] fp16 tile (+halo)
  __half2* hb = (__half2*)(sm + 3040);     // [3][76][32] col-pairs

  const int t = threadIdx.x;
  const int pl = blockIdx.z;    // b*64 + c
  const int b = pl >> 6, c = pl & 63;
  const int h0 = blockIdx.y << 6, w0 = blockIdx.x << 6;
  const float* xp = x + (size_t)pl * 65536;

  const __half2 W00 = __float2half2_rn(0.78698604f);
  const __half2 W01 = __float2half2_rn(0.10650698f);
  const __half2 W10 = __float2half2_rn(0.39905028f);
  const __half2 W11 = __float2half2_rn(0.24203623f);
  const __half2 W12 = __float2half2_rn(0.05400558f);
  const __half2 W13 = __float2half2_rn(0.00443305f);
  const __half2 W20 = __float2half2_rn(0.19967563f);
  const __half2 W21 = __float2half2_rn(0.17621312f);
  const __half2 W22 = __float2half2_rn(0.12110939f);
  const __half2 W23 = __float2half2_rn(0.06482519f);
  const __half2 W24 = __float2half2_rn(0.02702316f);
  const __half2 W25 = __float2half2_rn(0.00877314f);
  const __half2 W26 = __float2half2_rn(0.00221820f);

  for (int i = t; i < 5776; i += 256) {
    const int r = i / 76, cc = i - r * 76;
    const int hh = h0 - 6 + r, ww = w0 - 6 + cc;
    float v = 0.f;
    if ((unsigned)hh < 256u && (unsigned)ww < 256u) v = xp[hh * 256 + ww];
    sv[r * 80 + cc] = __float2half(v);
  }
  __syncthreads();

  // horizontal: 76 rows x 16 col-quads, all half2
  for (int i = t; i < 1216; i += 256) {
    const int r = i >> 4, jq = i & 15;
    const uint2* p = (const uint2*)((const char*)sv + r * 160 + (jq << 3));
    const uint2 q0 = p[0], q1 = p[1], q2 = p[2], q3 = p[3];
    const uint32_t H0 = q0.x, H1 = q0.y, H2 = q1.x, H3 = q1.y,
                   H4 = q2.x, H5 = q2.y, H6 = q3.x, H7 = q3.y;
    const uint32_t M0 = __byte_perm(H0, H1, 0x5432);
    const uint32_t M1 = __byte_perm(H1, H2, 0x5432);
    const uint32_t M2 = __byte_perm(H2, H3, 0x5432);
    const uint32_t M3 = __byte_perm(H3, H4, 0x5432);
    const uint32_t M4 = __byte_perm(H4, H5, 0x5432);
    const uint32_t M5 = __byte_perm(H5, H6, 0x5432);
    const uint32_t M6 = __byte_perm(H6, H7, 0x5432);

    // symmetric tap-pair sums (shared across all 3 scales)
    const __half2 T1A = __hadd2(u2h(M2), u2h(M3));
    const __half2 T2A = __hadd2(u2h(H2), u2h(H4));
    const __half2 T3A = __hadd2(u2h(M1), u2h(M4));
    const __half2 T4A = __hadd2(u2h(H1), u2h(H5));
    const __half2 T5A = __hadd2(u2h(M0), u2h(M5));
    const __half2 T6A = __hadd2(u2h(H0), u2h(H6));
    const __half2 T1B = __hadd2(u2h(M3), u2h(M4));
    const __half2 T2B = __hadd2(u2h(H3), u2h(H5));
    const __half2 T3B = __hadd2(u2h(M2), u2h(M5));
    const __half2 T4B = __hadd2(u2h(H2), u2h(H6));
    const __half2 T5B = __hadd2(u2h(M1), u2h(M6));
    const __half2 T6B = __hadd2(u2h(H1), u2h(H7));
    const __half2 CA = u2h(H3), CB = u2h(H4);

    const __half2 h0A = __hfma2(T1A, W01, __hmul2(CA, W00));
    const __half2 h0B = __hfma2(T1B, W01, __hmul2(CB, W00));
    const __half2 h1A = __hfma2(T3A, W13, __hfma2(T2A, W12,
                        __hfma2(T1A, W11, __hmul2(CA, W10))));
    const __half2 h1B = __hfma2(T3B, W13, __hfma2(T2B, W12,
                        __hfma2(T1B, W11, __hmul2(CB, W10))));
    const __half2 h2A = __hfma2(T6A, W26, __hfma2(T5A, W25, __hfma2(T4A, W24,
                        __hfma2(T3A, W23, __hfma2(T2A, W22,
                        __hfma2(T1A, W21, __hmul2(CA, W20)))))));
    const __half2 h2B = __hfma2(T6B, W26, __hfma2(T5B, W25, __hfma2(T4B, W24,
                        __hfma2(T3B, W23, __hfma2(T2B, W22,
                        __hfma2(T1B, W21, __hmul2(CB, W20)))))));

    *(uint2*)&hb[(0 * 76 + r) * 32 + (jq << 1)] = make_uint2(h2u(h0A), h2u(h0B));
    *(uint2*)&hb[(1 * 76 + r) * 32 + (jq << 1)] = make_uint2(h2u(h1A), h2u(h1B));
    *(uint2*)&hb[(2 * 76 + r) * 32 + (jq << 1)] = make_uint2(h2u(h2A), h2u(h2B));
  }
  __syncthreads();

  // vertical: thread = (col-pair jp, 8-row group rg); half2 sliding windows
  const int jp = t & 31, rg = t >> 5;
  const int base = rg << 3;
  const int pr2 = (w0 >> 1) + jp;
  __half2* y0 = (__half2*)(g_v + (size_t)(b * 192 + c) * 65536);
  __half2* y1 = (__half2*)(g_v + (size_t)(b * 192 + 64 + c) * 65536);
  __half2* y2 = (__half2*)(g_v + (size_t)(b * 192 + 128 + c) * 65536);

  __half2 a2[13], a1[7], a0[3];
  #pragma unroll
  for (int d = 0; d < 12; d++) a2[d] = hb[(2 * 76 + base + d) * 32 + jp];
  #pragma unroll
  for (int d = 0; d < 6; d++) a1[d] = hb[(1 * 76 + base + 3 + d) * 32 + jp];
  a0[0] = hb[(0 * 76 + base + 5) * 32 + jp];
  a0[1] = hb[(0 * 76 + base + 6) * 32 + jp];

  #pragma unroll
  for (int i2 = 0; i2 < 8; i2++) {
    a2[12] = hb[(2 * 76 + base + i2 + 12) * 32 + jp];
    a1[6]  = hb[(1 * 76 + base + i2 + 9) * 32 + jp];
    a0[2]  = hb[(0 * 76 + base + i2 + 7) * 32 + jp];
    const int row = (h0 + base + i2) * 128 + pr2;
    y0[row] = __hfma2(__hadd2(a0[0], a0[2]), W01, __hmul2(a0[1], W00));
    y1[row] = __hfma2(__hadd2(a1[0], a1[6]), W13,
              __hfma2(__hadd2(a1[1], a1[5]), W12,
              __hfma2(__hadd2(a1[2], a1[4]), W11, __hmul2(a1[3], W10))));
    y2[row] = __hfma2(__hadd2(a2[0], a2[12]), W26,
              __hfma2(__hadd2(a2[1], a2[11]), W25,
              __hfma2(__hadd2(a2[2], a2[10]), W24,
              __hfma2(__hadd2(a2[3], a2[9]),  W23,
              __hfma2(__hadd2(a2[4], a2[8]),  W22,
              __hfma2(__hadd2(a2[5], a2[7]),  W21, __hmul2(a2[6], W20)))))));
    #pragma unroll
    for (int d = 0; d < 12; d++) a2[d] = a2[d + 1];
    #pragma unroll
    for (int d = 0; d < 6; d++) a1[d] = a1[d + 1];
    a0[0] = a0[1]; a0[1] = a0[2];
  }
}

// ---------------------------------------------------------------------------
// Kernel 2: persistent fused 1x1 conv (R13-proven, unchanged).
// 296 CTAs (2/SM), B fragments staged once, A single-buffered with cross-tile
// cp.async overlap under the epilogue.
// ---------------------------------------------------------------------------
#define SA_STRH 136                        // halfs per k-row (272 B)
#define SMH_B   52224                      // 192*136*2
#define SMH_FB  76800                      // + 12*8*32*8
#define SMH_TOT 77056
#define NTILES  4096
#define NCTA    296

__global__ __launch_bounds__(256, 2) void fuse_mma_kernel(
    const float* __restrict__ x, const float* __restrict__ wf,
    const float* __restrict__ fb, float* __restrict__ out) {
  extern __shared__ char smc[];
  uint2* sB = (uint2*)(smc + SMH_B);       // [12][8][32] {k01, k89} half2 pairs
  float* sFB = (float*)(smc + SMH_FB);
  const uint32_t smbA = smem_u32(smc);

  const int t = threadIdx.x;
  const int lane = t & 31, w = t >> 5;
  const int g = lane >> 2, cc = lane & 3;

  if (t < 64) sFB[t] = fb[t];

  // B fragments once per CTA
  #pragma unroll
  for (int i = 0; i < 12; i++) {
    const int idx = i * 256 + t;
    const int kk = idx >> 8, rem = idx & 255;
    const int jj = rem >> 5, ln = rem & 31;
    const int o = (jj << 3) + (ln >> 2), kb = (kk << 4) + ((ln & 3) << 1);
    const float* wp = wf + o * 192 + kb;
    __half2 p0 = __floats2half2_rn(wp[0], wp[1]);
    __half2 p1 = __floats2half2_rn(wp[8], wp[9]);
    sB[idx] = make_uint2(h2u(p0), h2u(p1));
  }

  // prefetch A for first tile
  {
    const int tile = blockIdx.x;
    const __half* yb = g_v + ((size_t)(tile >> 9) * 192 * 65536) +
                       ((tile & 511) << 7);
    #pragma unroll
    for (int i = 0; i < 12; i++) {
      const int idx = i * 256 + t;
      const int k = idx >> 4, c = idx & 15;
      const uint32_t dst = smbA + k * 272 + c * 16;
      asm volatile("cp.async.cg.shared.global [%0], [%1], 16;"
                   :: "r"(dst), "l"(yb + (size_t)k * 65536 + c * 8));
    }
    asm volatile("cp.async.commit_group;");
  }

  const int row8 = lane & 7;
  const int px_add = ((lane >> 3) & 1) << 3;
  const int k_add = (lane >> 4) << 3;
  const uint32_t a_addr0 =
      smbA + ((k_add + row8) * SA_STRH + (w << 4) + px_add) * 2;

  for (int tile = blockIdx.x; tile < NTILES; tile += NCTA) {
    const int b = tile >> 9;
    const int px0 = (tile & 511) << 7;

    asm volatile("cp.async.wait_group 0;");
    __syncthreads();

    float acc[8][4];
    #pragma unroll
    for (int j = 0; j < 8; j++)
      #pragma unroll
      for (int q = 0; q < 4; q++) acc[j][q] = 0.f;

    uint32_t a_addr = a_addr0;
    #pragma unroll
    for (int kk = 0; kk < 12; kk++) {
      uint32_t a0, a1, a2, a3;
      asm volatile(
          "ldmatrix.sync.aligned.m8n8.x4.trans.shared.b16 {%0,%1,%2,%3}, [%4];"
          : "=r"(a0), "=r"(a1), "=r"(a2), "=r"(a3) : "r"(a_addr));
      a_addr += 16 * SA_STRH * 2;
      const uint2* bp = sB + (kk << 8) + lane;
      #pragma unroll
      for (int j = 0; j < 8; j++) {
        const uint2 bv = bp[j << 5];
        asm volatile(
            "mma.sync.aligned.m16n8k16.row.col.f32.f16.f16.f32 "
            "{%0,%1,%2,%3}, {%4,%5,%6,%7}, {%8,%9}, {%0,%1,%2,%3};"
            : "+f"(acc[j][0]), "+f"(acc[j][1]), "+f"(acc[j][2]), "+f"(acc[j][3])
            : "r"(a0), "r"(a1), "r"(a2), "r"(a3), "r"(bv.x), "r"(bv.y));
      }
    }

    __syncthreads();   // all warps done reading sA

    // prefetch next tile's A — DMA overlaps the epilogue below
    const int ntile = tile + NCTA;
    if (ntile < NTILES) {
      const __half* yb = g_v + ((size_t)(ntile >> 9) * 192 * 65536) +
                         ((ntile & 511) << 7);
      #pragma unroll
      for (int i = 0; i < 12; i++) {
        const int idx = i * 256 + t;
        const int k = idx >> 4, c = idx & 15;
        const uint32_t dst = smbA + k * 272 + c * 16;
        asm volatile("cp.async.cg.shared.global [%0], [%1], 16;"
                     :: "r"(dst), "l"(yb + (size_t)k * 65536 + c * 8));
      }
    }
    asm volatile("cp.async.commit_group;");

    // epilogue: thread holds rows pxg, pxg+8; cols o0=8j+2c, o1=o0+1
    const int pxg = px0 + (w << 4) + g;
    const size_t bb = (size_t)(b << 6) * 65536;
    #pragma unroll
    for (int j = 0; j < 8; j++) {
      const int o0 = (j << 3) + (cc << 1), o1 = o0 + 1;
      const float fb0 = sFB[o0], fb1 = sFB[o1];
      const size_t a0i = bb + (size_t)o0 * 65536 + pxg;
      const size_t a1i = bb + (size_t)o1 * 65536 + pxg;
      out[a0i]     = x[a0i]     + fb0 + acc[j][0];
      out[a1i]     = x[a1i]     + fb1 + acc[j][1];
      out[a0i + 8] = x[a0i + 8] + fb0 + acc[j][2];
      out[a1i + 8] = x[a1i + 8] + fb1 + acc[j][3];
    }
  }
}

// ---------------------------------------------------------------------------
extern "C" void kernel_launch(void* const* d_in, const int* in_sizes, int n_in,
                              void* d_out, int out_size) {
  const float* x  = (const float*)d_in[0];   // [8,64,256,256] f32
  const float* wf = (const float*)d_in[1];   // [64,192] f32
  const float* fb = (const float*)d_in[2];   // [64] f32
  float* out = (float*)d_out;                // [8,64,256,256] f32

  cudaFuncSetAttribute(blur_kernel,
                       cudaFuncAttributeMaxDynamicSharedMemorySize, 41344);
  blur_kernel<<<dim3(4, 4, 512), 256, 41344>>>(x);

  cudaFuncSetAttribute(fuse_mma_kernel,
                       cudaFuncAttributeMaxDynamicSharedMemorySize, SMH_TOT);
  fuse_mma_kernel<<<NCTA, 256, SMH_TOT>>>(x, wf, fb, out);
}